// round 2
// baseline (speedup 1.0000x reference)
#include <cuda_runtime.h>
#include <math_constants.h>

// Problem constants
#define DMODEL 1024
#define NHEADS 16
#define DK 64
#define DV 64
#define BATCH 2
#define TSEQ 2048
#define BT (BATCH * TSEQ)                  // 4096
#define OUT_ELEMS ((long long)BT * DMODEL) // 4194304 (output region size)

// Scratch (static device memory; allocation APIs are forbidden)
__device__ float g_Q[BT * DMODEL];
__device__ float g_K[BT * DMODEL];
__device__ float g_V[BT * DMODEL];
__device__ float g_O[BT * DMODEL];

// ---------------------------------------------------------------------------
// Generic tiled GEMM:  C[m][n] = epi( sum_k A[m*lda+k] * Bel(n,k) )
//   BKC = true : Bel(n,k) = Bm[n*ldb + k]   (B rows are K-contiguous; C = A B^T)
//   BKC = false: Bel(n,k) = Bm[k*ldb + n]   (B rows are N-contiguous; C = A B)
//   EPI = 0: plain store
//   EPI = 1: v = v*scale; if (mask[b*T + n]) v = -inf   (attention scores)
// mask is int32 (harness ships bool as int32).
// Block tile 64x64, 256 threads, 4x4 per-thread register tile, k-chunk 16.
// ---------------------------------------------------------------------------
template <bool BKC, int EPI>
__global__ __launch_bounds__(256) void gemm64(
    const float* __restrict__ A, int lda, long long sAb, long long sAh,
    const float* __restrict__ Bm, int ldb, long long sBb, long long sBh,
    float* __restrict__ C, int ldc, long long sCb, long long sCh,
    int Kd, int Hn, float scale, const int* __restrict__ mask)
{
    __shared__ float sA[16][68];
    __shared__ float sB[16][68];

    const int z = blockIdx.z;
    const int b = z / Hn;
    const int h = z - b * Hn;
    A  += b * sAb + h * sAh;
    Bm += b * sBb + h * sBh;
    C  += b * sCb + h * sCh;

    const int tid = threadIdx.x;        // 0..255
    const int tx  = tid & 15;           // 0..15 (n groups of 4)
    const int ty  = tid >> 4;           // 0..15 (m groups of 4)
    const int m0  = blockIdx.y << 6;
    const int n0  = blockIdx.x << 6;

    const int lr = tid >> 2;            // 0..63 tile row for loads
    const int lq = tid & 3;             // which float4 in the 16-wide k-chunk

    float acc[4][4];
#pragma unroll
    for (int i = 0; i < 4; i++)
#pragma unroll
        for (int j = 0; j < 4; j++) acc[i][j] = 0.f;

    for (int k0 = 0; k0 < Kd; k0 += 16) {
        // A tile: row (m0+lr), k = k0 + 4*lq .. +3  -> transposed into sA[k][m]
        float4 a4 = *(const float4*)(A + (long long)(m0 + lr) * lda + (k0 + 4 * lq));
        sA[4 * lq + 0][lr] = a4.x;
        sA[4 * lq + 1][lr] = a4.y;
        sA[4 * lq + 2][lr] = a4.z;
        sA[4 * lq + 3][lr] = a4.w;

        if (BKC) {
            float4 b4 = *(const float4*)(Bm + (long long)(n0 + lr) * ldb + (k0 + 4 * lq));
            sB[4 * lq + 0][lr] = b4.x;
            sB[4 * lq + 1][lr] = b4.y;
            sB[4 * lq + 2][lr] = b4.z;
            sB[4 * lq + 3][lr] = b4.w;
        } else {
            const int kk = tid >> 4;    // 0..15
            const int nq = tid & 15;    // 0..15 -> n = 4*nq
            float4 b4 = *(const float4*)(Bm + (long long)(k0 + kk) * ldb + (n0 + 4 * nq));
            *(float4*)&sB[kk][4 * nq] = b4;
        }
        __syncthreads();

#pragma unroll
        for (int kk = 0; kk < 16; kk++) {
            float4 av = *(const float4*)&sA[kk][4 * ty];
            float4 bv = *(const float4*)&sB[kk][4 * tx];
            float am[4] = {av.x, av.y, av.z, av.w};
            float bn[4] = {bv.x, bv.y, bv.z, bv.w};
#pragma unroll
            for (int i = 0; i < 4; i++)
#pragma unroll
                for (int j = 0; j < 4; j++)
                    acc[i][j] = fmaf(am[i], bn[j], acc[i][j]);
        }
        __syncthreads();
    }

#pragma unroll
    for (int i = 0; i < 4; i++) {
        const int m = m0 + 4 * ty + i;
#pragma unroll
        for (int j = 0; j < 4; j++) {
            const int n = n0 + 4 * tx + j;
            float v = acc[i][j];
            if (EPI == 1) {
                v *= scale;
                if (mask[b * TSEQ + n] != 0) v = -CUDART_INF_F;
            }
            C[(long long)m * ldc + n] = v;
        }
    }
}

// ---------------------------------------------------------------------------
// Row softmax, in place, over T=2048 columns. One block (256 threads) per row.
// Masked entries arrive as -inf; fully-masked row -> all zeros (nan_to_num).
// ---------------------------------------------------------------------------
__global__ __launch_bounds__(256) void softmax_rows(float* __restrict__ Wt)
{
    const long long row = blockIdx.x;
    float* p = Wt + row * (long long)TSEQ;
    const int tid = threadIdx.x;
    const int lane = tid & 31, wid = tid >> 5;

    float4 v0 = ((const float4*)p)[tid];
    float4 v1 = ((const float4*)p)[tid + 256];

    float m = fmaxf(fmaxf(fmaxf(v0.x, v0.y), fmaxf(v0.z, v0.w)),
                    fmaxf(fmaxf(v1.x, v1.y), fmaxf(v1.z, v1.w)));
#pragma unroll
    for (int o = 16; o > 0; o >>= 1) m = fmaxf(m, __shfl_xor_sync(0xffffffffu, m, o));

    __shared__ float sm[8];
    if (lane == 0) sm[wid] = m;
    __syncthreads();
    if (tid == 0) {
        float t = sm[0];
        for (int i = 1; i < 8; i++) t = fmaxf(t, sm[i]);
        sm[0] = t;
    }
    __syncthreads();
    m = sm[0];

    // exp with -inf guard (also covers fully-masked rows where m == -inf)
    v0.x = (v0.x == -CUDART_INF_F) ? 0.f : __expf(v0.x - m);
    v0.y = (v0.y == -CUDART_INF_F) ? 0.f : __expf(v0.y - m);
    v0.z = (v0.z == -CUDART_INF_F) ? 0.f : __expf(v0.z - m);
    v0.w = (v0.w == -CUDART_INF_F) ? 0.f : __expf(v0.w - m);
    v1.x = (v1.x == -CUDART_INF_F) ? 0.f : __expf(v1.x - m);
    v1.y = (v1.y == -CUDART_INF_F) ? 0.f : __expf(v1.y - m);
    v1.z = (v1.z == -CUDART_INF_F) ? 0.f : __expf(v1.z - m);
    v1.w = (v1.w == -CUDART_INF_F) ? 0.f : __expf(v1.w - m);

    float s = v0.x + v0.y + v0.z + v0.w + v1.x + v1.y + v1.z + v1.w;
#pragma unroll
    for (int o = 16; o > 0; o >>= 1) s += __shfl_xor_sync(0xffffffffu, s, o);

    __shared__ float ss[8];
    if (lane == 0) ss[wid] = s;
    __syncthreads();
    if (tid == 0) {
        float t = 0.f;
        for (int i = 0; i < 8; i++) t += ss[i];
        ss[0] = t;
    }
    __syncthreads();
    const float tot = ss[0];
    const float inv = (tot > 0.f) ? (1.f / tot) : 0.f;

    v0.x *= inv; v0.y *= inv; v0.z *= inv; v0.w *= inv;
    v1.x *= inv; v1.y *= inv; v1.z *= inv; v1.w *= inv;
    ((float4*)p)[tid] = v0;
    ((float4*)p)[tid + 256] = v1;
}

// ---------------------------------------------------------------------------
// kernel_launch: x, mask, W_Q, W_K, W_V, W_O  ->  d_out = [output | weights]
// ---------------------------------------------------------------------------
extern "C" void kernel_launch(void* const* d_in, const int* in_sizes, int n_in,
                              void* d_out, int out_size)
{
    const float* x    = (const float*)d_in[0];
    const int*   mask = (const int*)d_in[1];                 // (B,1,1,T) bool -> int32
    const float* WQ   = (const float*)d_in[2];               // (H, DK, DMODEL)
    const float* WK   = (const float*)d_in[3];
    const float* WV   = (const float*)d_in[4];
    const float* WO   = (const float*)d_in[5];               // (DMODEL, H*DV)

    float* out = (float*)d_out;            // (B, T, DMODEL)
    float* wts = out + OUT_ELEMS;          // (B, H, T, T)

    float *Q, *K, *V, *O;
    cudaGetSymbolAddress((void**)&Q, g_Q);
    cudaGetSymbolAddress((void**)&K, g_K);
    cudaGetSymbolAddress((void**)&V, g_V);
    cudaGetSymbolAddress((void**)&O, g_O);

    const dim3 blk(256);

    // 1) QKV projections: (BT x DMODEL) @ (DMODEL x DMODEL)^T -> [bt][h*64+k]
    {
        const dim3 grd(DMODEL / 64, BT / 64, 1);
        gemm64<true, 0><<<grd, blk>>>(x, DMODEL, 0, 0, WQ, DMODEL, 0, 0,
                                      Q, DMODEL, 0, 0, DMODEL, 1, 1.f, nullptr);
        gemm64<true, 0><<<grd, blk>>>(x, DMODEL, 0, 0, WK, DMODEL, 0, 0,
                                      K, DMODEL, 0, 0, DMODEL, 1, 1.f, nullptr);
        gemm64<true, 0><<<grd, blk>>>(x, DMODEL, 0, 0, WV, DMODEL, 0, 0,
                                      V, DMODEL, 0, 0, DMODEL, 1, 1.f, nullptr);
    }

    // 2) Scores: per (b,h): (T x dk) @ (T x dk)^T * scale, mask -> -inf
    {
        const dim3 grd(TSEQ / 64, TSEQ / 64, BATCH * NHEADS);
        const long long sQ = (long long)TSEQ * DMODEL;   // per-batch stride
        gemm64<true, 1><<<grd, blk>>>(
            Q, DMODEL, sQ, DK,
            K, DMODEL, sQ, DK,
            wts, TSEQ, (long long)NHEADS * TSEQ * TSEQ, (long long)TSEQ * TSEQ,
            DK, NHEADS, 0.125f /* 1/sqrt(64) */, mask);
    }

    // 3) Softmax in place over last axis (B*H*T rows)
    softmax_rows<<<BATCH * NHEADS * TSEQ, blk>>>(wts);

    // 4) PV: per (b,h): (T x T) @ (T x dv) -> O[bt][h*64+v]
    {
        const dim3 grd(DV / 64, TSEQ / 64, BATCH * NHEADS);
        gemm64<false, 0><<<grd, blk>>>(
            wts, TSEQ, (long long)NHEADS * TSEQ * TSEQ, (long long)TSEQ * TSEQ,
            V, DMODEL, (long long)TSEQ * DMODEL, DV,
            O, DMODEL, (long long)TSEQ * DMODEL, DV,
            TSEQ, NHEADS, 1.f, nullptr);
    }

    // 5) Output projection: (BT x 1024) @ W_O^T -> output
    {
        const dim3 grd(DMODEL / 64, BT / 64, 1);
        gemm64<true, 0><<<grd, blk>>>(O, DMODEL, 0, 0, WO, DMODEL, 0, 0,
                                      out, DMODEL, 0, 0, NHEADS * DV, 1, 1.f, nullptr);
    }
}

// round 4
// speedup vs baseline: 1.9715x; 1.9715x over previous
#include <cuda_runtime.h>
#include <cstdint>

// ---------------------------------------------------------------------------
// Problem constants
// ---------------------------------------------------------------------------
#define DMODEL 1024
#define NHEADS 16
#define HD     64
#define BATCH  2
#define TSEQ   2048
#define BT     4096
#define NROWS  65536
#define NSLAB  32
#define OUT_ELEMS 4194304LL

// Scratch (static device memory; allocation APIs are forbidden)
__device__ float g_Q[BT * DMODEL];      // (B,H,T,64)
__device__ float g_K[BT * DMODEL];      // (B,H,T,64)
__device__ float g_V[BT * DMODEL];      // (B,H,T,64)
__device__ float g_O[BT * DMODEL];      // (B,T,H*64)
__device__ float g_psum[(long long)NROWS * NSLAB];
__device__ float g_inv[NROWS];

// ---------------------------------------------------------------------------
// bf16 helpers
// ---------------------------------------------------------------------------
__device__ __forceinline__ void cvt2(float x0, float x1, uint32_t& hp, uint32_t& lp) {
    // hp = {lo=bf16(x0), hi=bf16(x1)}; lp packs the residuals
    asm("cvt.rn.bf16x2.f32 %0, %1, %2;" : "=r"(hp) : "f"(x1), "f"(x0));
    float h0 = __uint_as_float(hp << 16);
    float h1 = __uint_as_float(hp & 0xFFFF0000u);
    asm("cvt.rn.bf16x2.f32 %0, %1, %2;" : "=r"(lp) : "f"(x1 - h1), "f"(x0 - h0));
}

__device__ __forceinline__ void mma_bf16(float* c, const uint32_t* a, const uint32_t* b) {
    asm volatile(
        "mma.sync.aligned.m16n8k16.row.col.f32.bf16.bf16.f32 "
        "{%0,%1,%2,%3}, {%4,%5,%6,%7}, {%8,%9}, {%0,%1,%2,%3};"
        : "+f"(c[0]), "+f"(c[1]), "+f"(c[2]), "+f"(c[3])
        : "r"(a[0]), "r"(a[1]), "r"(a[2]), "r"(a[3]), "r"(b[0]), "r"(b[1]));
}

// ---------------------------------------------------------------------------
// bf16x3 warp-MMA GEMM.  C(128 x BN per CTA) = A(M,K) * B(N,K)^T
// EPI: 0=plain  1=QKV routing  2=scores exp+mask+psum  3=PV (O scaled by inv)
// BTRANS: B gmem is [k][n]; transpose into SMEM during stores (PV's V).
// WRITE_W: while loading A(=E), write normalized weights E*inv in place.
// 8 warps: warp grid 4(M) x 2(N); warp tile 32 x BN/2. k-chunk 32, 2 stages.
// ---------------------------------------------------------------------------
template <int BN, int EPI, bool BTRANS, bool WRITE_W>
__global__ __launch_bounds__(256) void gemm_mma(
    const float* __restrict__ A, long long lda, long long zA,
    const float* __restrict__ B0, const float* __restrict__ B1, const float* __restrict__ B2,
    long long ldb, long long zB,
    float* __restrict__ C, long long ldc, long long zC,
    int Kd, const int* __restrict__ mask, const float* __restrict__ inv,
    float* __restrict__ psum)
{
    constexpr int SAP = 40;                 // padded SMEM row stride (bf16 elems)
    constexpr int ASZ = 128 * SAP;
    constexpr int BSZ = BN * SAP;
    constexpr int STG = 2 * (ASZ + BSZ);    // elems per stage (Ah,Al,Bh,Bl)
    constexpr int NF  = BN / 16;            // n-frags per warp (warpN/8)
    constexpr int NB4 = (BN * 8) / 256;     // standard-path B float4 per thread
    constexpr int NBR = BTRANS ? 2 : NB4;

    extern __shared__ unsigned short smem[];

    const int tid = threadIdx.x, lane = tid & 31, wid = tid >> 5;
    const int g = lane >> 2, t4 = lane & 3;
    const int wm0 = (wid >> 1) * 32;
    const int wni = wid & 1;
    const int wn0 = wni * (BN / 2);
    const int z = blockIdx.z, m0 = blockIdx.y * 128, n0 = blockIdx.x * BN;

    const float* Ab = A + (long long)z * zA;
    const float* Bb;
    if (EPI == 1) {
        const int mat = blockIdx.x >> 3;
        const float* Bs = (mat == 0) ? B0 : ((mat == 1) ? B1 : B2);
        Bb = Bs + (long long)((blockIdx.x & 7) * 128) * ldb;
    } else if (BTRANS) {
        Bb = B0 + (long long)z * zB + n0;
    } else {
        Bb = B0 + (long long)z * zB + (long long)n0 * ldb;
    }

    float acc[2][NF][4];
#pragma unroll
    for (int mi = 0; mi < 2; ++mi)
#pragma unroll
        for (int ni = 0; ni < NF; ++ni)
#pragma unroll
            for (int j = 0; j < 4; ++j) acc[mi][ni][j] = 0.f;

    float4 aR[4];
    float4 bR[NBR];

    auto loadA = [&](int s) {
        const int k0 = s << 5;
#pragma unroll
        for (int i = 0; i < 4; ++i) {
            const int idx = tid + 256 * i, r = idx >> 3, q = idx & 7;
            const float* p = Ab + (long long)(m0 + r) * lda + (k0 + 4 * q);
            aR[i] = *(const float4*)p;
            if (WRITE_W) {
                const float iv = inv[(long long)z * TSEQ + m0 + r];
                *(float4*)(const_cast<float*>(p)) =
                    make_float4(aR[i].x * iv, aR[i].y * iv, aR[i].z * iv, aR[i].w * iv);
            }
        }
    };

    auto loadB = [&](int s) {
        const int k0 = s << 5;
        if (BTRANS) {
#pragma unroll
            for (int i = 0; i < 2; ++i) {
                const int idx = tid + 256 * i, c4 = idx >> 5, r = idx & 31;
                bR[i] = *(const float4*)(Bb + (long long)(k0 + r) * ldb + 4 * c4);
            }
        } else {
#pragma unroll
            for (int i = 0; i < NB4; ++i) {
                const int idx = tid + 256 * i, r = idx >> 3, q = idx & 7;
                bR[i] = *(const float4*)(Bb + (long long)r * ldb + (k0 + 4 * q));
            }
        }
    };

    auto stsA = [&](int st) {
        unsigned short* Ah = smem + st * STG;
        unsigned short* Al = Ah + ASZ;
#pragma unroll
        for (int i = 0; i < 4; ++i) {
            const int idx = tid + 256 * i, r = idx >> 3, q = idx & 7;
            uint32_t h01, l01, h23, l23;
            cvt2(aR[i].x, aR[i].y, h01, l01);
            cvt2(aR[i].z, aR[i].w, h23, l23);
            *(uint2*)(Ah + r * SAP + 4 * q) = make_uint2(h01, h23);
            *(uint2*)(Al + r * SAP + 4 * q) = make_uint2(l01, l23);
        }
    };

    auto stsB = [&](int st) {
        unsigned short* Bh = smem + st * STG + 2 * ASZ;
        unsigned short* Bl = Bh + BSZ;
        if (BTRANS) {
#pragma unroll
            for (int i = 0; i < 2; ++i) {
                const int idx = tid + 256 * i, c4 = idx >> 5, r = idx & 31;
                uint32_t h01, l01, h23, l23;
                cvt2(bR[i].x, bR[i].y, h01, l01);
                cvt2(bR[i].z, bR[i].w, h23, l23);
                Bh[(4 * c4 + 0) * SAP + r] = (unsigned short)(h01 & 0xFFFF);
                Bh[(4 * c4 + 1) * SAP + r] = (unsigned short)(h01 >> 16);
                Bh[(4 * c4 + 2) * SAP + r] = (unsigned short)(h23 & 0xFFFF);
                Bh[(4 * c4 + 3) * SAP + r] = (unsigned short)(h23 >> 16);
                Bl[(4 * c4 + 0) * SAP + r] = (unsigned short)(l01 & 0xFFFF);
                Bl[(4 * c4 + 1) * SAP + r] = (unsigned short)(l01 >> 16);
                Bl[(4 * c4 + 2) * SAP + r] = (unsigned short)(l23 & 0xFFFF);
                Bl[(4 * c4 + 3) * SAP + r] = (unsigned short)(l23 >> 16);
            }
        } else {
#pragma unroll
            for (int i = 0; i < NB4; ++i) {
                const int idx = tid + 256 * i, r = idx >> 3, q = idx & 7;
                uint32_t h01, l01, h23, l23;
                cvt2(bR[i].x, bR[i].y, h01, l01);
                cvt2(bR[i].z, bR[i].w, h23, l23);
                *(uint2*)(Bh + r * SAP + 4 * q) = make_uint2(h01, h23);
                *(uint2*)(Bl + r * SAP + 4 * q) = make_uint2(l01, l23);
            }
        }
    };

    auto compute = [&](int st) {
        const unsigned short* Ah = smem + st * STG;
        const unsigned short* Al = Ah + ASZ;
        const unsigned short* Bh = Ah + 2 * ASZ;
        const unsigned short* Bl = Bh + BSZ;
#pragma unroll
        for (int ks = 0; ks < 2; ++ks) {
            uint32_t ah[2][4], al[2][4], bh[NF][2], bl[NF][2];
#pragma unroll
            for (int mi = 0; mi < 2; ++mi) {
                const int ro = (wm0 + 16 * mi + g) * SAP + 16 * ks + 2 * t4;
                ah[mi][0] = *(const uint32_t*)(Ah + ro);
                ah[mi][1] = *(const uint32_t*)(Ah + ro + 8 * SAP);
                ah[mi][2] = *(const uint32_t*)(Ah + ro + 8);
                ah[mi][3] = *(const uint32_t*)(Ah + ro + 8 * SAP + 8);
                al[mi][0] = *(const uint32_t*)(Al + ro);
                al[mi][1] = *(const uint32_t*)(Al + ro + 8 * SAP);
                al[mi][2] = *(const uint32_t*)(Al + ro + 8);
                al[mi][3] = *(const uint32_t*)(Al + ro + 8 * SAP + 8);
            }
#pragma unroll
            for (int ni = 0; ni < NF; ++ni) {
                const int ro = (wn0 + 8 * ni + g) * SAP + 16 * ks + 2 * t4;
                bh[ni][0] = *(const uint32_t*)(Bh + ro);
                bh[ni][1] = *(const uint32_t*)(Bh + ro + 8);
                bl[ni][0] = *(const uint32_t*)(Bl + ro);
                bl[ni][1] = *(const uint32_t*)(Bl + ro + 8);
            }
#pragma unroll
            for (int mi = 0; mi < 2; ++mi)
#pragma unroll
                for (int ni = 0; ni < NF; ++ni) {
                    mma_bf16(acc[mi][ni], ah[mi], bh[ni]);
                    mma_bf16(acc[mi][ni], ah[mi], bl[ni]);
                    mma_bf16(acc[mi][ni], al[mi], bh[ni]);
                }
        }
    };

    // ---- pipelined main loop ----
    const int nS = Kd >> 5;
    loadA(0); loadB(0);
    stsA(0);  stsB(0);
    __syncthreads();
    for (int s = 0; s < nS; ++s) {
        const int st = s & 1;
        if (s + 1 < nS) { loadA(s + 1); loadB(s + 1); }
        compute(st);
        __syncthreads();
        if (s + 1 < nS) { stsA(st ^ 1); stsB(st ^ 1); __syncthreads(); }
    }

    // ---- epilogue ----
    float rs[4] = {0.f, 0.f, 0.f, 0.f};
    const int gb = z >> 4;
#pragma unroll
    for (int mi = 0; mi < 2; ++mi) {
        const int r0 = wm0 + 16 * mi + g, r1 = r0 + 8;
        float iv0 = 0.f, iv1 = 0.f;
        if (EPI == 3) {
            iv0 = inv[(long long)z * TSEQ + m0 + r0];
            iv1 = inv[(long long)z * TSEQ + m0 + r1];
        }
#pragma unroll
        for (int ni = 0; ni < NF; ++ni) {
            const int c = wn0 + 8 * ni + 2 * t4;
            const float v0 = acc[mi][ni][0], v1 = acc[mi][ni][1];
            const float v2 = acc[mi][ni][2], v3 = acc[mi][ni][3];
            if (EPI == 0) {
                float* Cz = C + (long long)z * zC;
                *(float2*)(Cz + (long long)(m0 + r0) * ldc + n0 + c) = make_float2(v0, v1);
                *(float2*)(Cz + (long long)(m0 + r1) * ldc + n0 + c) = make_float2(v2, v3);
            } else if (EPI == 1) {
                const int nloc = (blockIdx.x & 7) * 128 + c;
                const int h = nloc >> 6, k = nloc & 63;
                const int mat = blockIdx.x >> 3;
                float* dst = (mat == 0) ? g_Q : ((mat == 1) ? g_K : g_V);
                const int mr0 = m0 + r0, b0 = mr0 >> 11, tt0 = mr0 & 2047;
                const int mr1 = m0 + r1, b1 = mr1 >> 11, tt1 = mr1 & 2047;
                *(float2*)(dst + ((long long)((b0 * 16 + h) * 2048 + tt0)) * 64 + k) = make_float2(v0, v1);
                *(float2*)(dst + ((long long)((b1 * 16 + h) * 2048 + tt1)) * 64 + k) = make_float2(v2, v3);
            } else if (EPI == 2) {
                const int mk0 = mask[gb * TSEQ + n0 + c];
                const int mk1 = mask[gb * TSEQ + n0 + c + 1];
                const float e0 = mk0 ? 0.f : __expf(v0 * 0.125f);
                const float e1 = mk1 ? 0.f : __expf(v1 * 0.125f);
                const float e2 = mk0 ? 0.f : __expf(v2 * 0.125f);
                const float e3 = mk1 ? 0.f : __expf(v3 * 0.125f);
                float* Cz = C + (long long)z * zC;
                *(float2*)(Cz + (long long)(m0 + r0) * ldc + n0 + c) = make_float2(e0, e1);
                *(float2*)(Cz + (long long)(m0 + r1) * ldc + n0 + c) = make_float2(e2, e3);
                rs[2 * mi]     += e0 + e1;
                rs[2 * mi + 1] += e2 + e3;
            } else { // EPI == 3
                const long long base0 = ((long long)((z >> 4) * TSEQ + m0 + r0)) * 1024 + (z & 15) * 64;
                const long long base1 = ((long long)((z >> 4) * TSEQ + m0 + r1)) * 1024 + (z & 15) * 64;
                *(float2*)(g_O + base0 + c) = make_float2(v0 * iv0, v1 * iv0);
                *(float2*)(g_O + base1 + c) = make_float2(v2 * iv1, v3 * iv1);
            }
        }
    }
    if (EPI == 2) {
#pragma unroll
        for (int j = 0; j < 4; ++j) {
            float sv = rs[j];
            sv += __shfl_xor_sync(0xffffffffu, sv, 1);
            sv += __shfl_xor_sync(0xffffffffu, sv, 2);
            if (t4 == 0) {
                const int row = m0 + wm0 + 16 * (j >> 1) + g + 8 * (j & 1);
                psum[((long long)z * TSEQ + row) * NSLAB + blockIdx.x * 2 + wni] = sv;
            }
        }
    }
}

// Deterministic row-sum reduction: inv = sum>0 ? 1/sum : 0
__global__ __launch_bounds__(256) void reduce_inv(const float* __restrict__ psum,
                                                  float* __restrict__ inv) {
    const int r = blockIdx.x * 256 + threadIdx.x;
    if (r < NROWS) {
        float s = 0.f;
#pragma unroll
        for (int i = 0; i < NSLAB; ++i) s += psum[(long long)r * NSLAB + i];
        inv[r] = (s > 0.f) ? (1.f / s) : 0.f;
    }
}

// ---------------------------------------------------------------------------
// kernel_launch: x, mask(int32), W_Q, W_K, W_V, W_O -> d_out = [output | weights]
// ---------------------------------------------------------------------------
extern "C" void kernel_launch(void* const* d_in, const int* in_sizes, int n_in,
                              void* d_out, int out_size)
{
    const float* x    = (const float*)d_in[0];
    const int*   mask = (const int*)d_in[1];
    const float* WQ   = (const float*)d_in[2];
    const float* WK   = (const float*)d_in[3];
    const float* WV   = (const float*)d_in[4];
    const float* WO   = (const float*)d_in[5];

    float* out = (float*)d_out;
    float* wts = out + OUT_ELEMS;

    float *Qp, *Kp, *Vp, *Op, *psum, *invp;
    cudaGetSymbolAddress((void**)&Qp,   g_Q);
    cudaGetSymbolAddress((void**)&Kp,   g_K);
    cudaGetSymbolAddress((void**)&Vp,   g_V);
    cudaGetSymbolAddress((void**)&Op,   g_O);
    cudaGetSymbolAddress((void**)&psum, g_psum);
    cudaGetSymbolAddress((void**)&invp, g_inv);

    const int SM128 = 2 * 2 * (128 * 40 + 128 * 40) * 2;  // 81920 bytes
    const int SM64  = 2 * 2 * (128 * 40 + 64 * 40) * 2;   // 61440 bytes
    cudaFuncSetAttribute(gemm_mma<128, 1, false, false>, cudaFuncAttributeMaxDynamicSharedMemorySize, SM128);
    cudaFuncSetAttribute(gemm_mma<128, 2, false, false>, cudaFuncAttributeMaxDynamicSharedMemorySize, SM128);
    cudaFuncSetAttribute(gemm_mma<64,  3, true,  true >, cudaFuncAttributeMaxDynamicSharedMemorySize, SM64);
    cudaFuncSetAttribute(gemm_mma<128, 0, false, false>, cudaFuncAttributeMaxDynamicSharedMemorySize, SM128);

    const long long TT = (long long)TSEQ * TSEQ;

    // 1) Fused QKV: (4096 x 1024) x {WQ,WK,WV}^T -> g_Q/g_K/g_V (b,h,t,64)
    gemm_mma<128, 1, false, false><<<dim3(24, 32, 1), 256, SM128>>>(
        x, DMODEL, 0, WQ, WK, WV, DMODEL, 0,
        nullptr, 0, 0, DMODEL, nullptr, nullptr, nullptr);

    // 2) Scores -> E = exp(0.125*QK^T) (masked->0) into wts, + partial row sums
    gemm_mma<128, 2, false, false><<<dim3(16, 16, 32), 256, SM128>>>(
        Qp, HD, (long long)TSEQ * HD, Kp, nullptr, nullptr, HD, (long long)TSEQ * HD,
        wts, TSEQ, TT, HD, mask, nullptr, psum);

    // 3) Row sums -> inv
    reduce_inv<<<NROWS / 256, 256>>>(psum, invp);

    // 4) PV: O = (E V) * inv ; rewrites normalized weights E*inv in place
    gemm_mma<64, 3, true, true><<<dim3(1, 16, 32), 256, SM64>>>(
        wts, TSEQ, TT, Vp, nullptr, nullptr, HD, (long long)TSEQ * HD,
        nullptr, 0, 0, TSEQ, nullptr, invp, nullptr);

    // 5) Output projection: (4096 x 1024) x WO^T -> out
    gemm_mma<128, 0, false, false><<<dim3(8, 32, 1), 256, SM128>>>(
        Op, DMODEL, 0, WO, nullptr, nullptr, DMODEL, 0,
        out, DMODEL, 0, DMODEL, nullptr, nullptr, nullptr);
}

// round 5
// speedup vs baseline: 2.1016x; 1.0660x over previous
#include <cuda_runtime.h>
#include <cstdint>

// ---------------------------------------------------------------------------
// Problem constants
// ---------------------------------------------------------------------------
#define DMODEL 1024
#define NHEADS 16
#define HD     64
#define BATCH  2
#define TSEQ   2048
#define BT     4096
#define NROWS  65536
#define OUT_ELEMS 4194304LL

// Scratch (static device memory; allocation APIs are forbidden)
__device__ float g_Q[BT * DMODEL];      // (B,H,T,64)
__device__ float g_K[BT * DMODEL];      // (B,H,T,64)
__device__ float g_V[BT * DMODEL];      // (B,H,T,64)
__device__ float g_O[BT * DMODEL];      // (B,T,H*64)
__device__ float g_inv[NROWS];

// ---------------------------------------------------------------------------
// bf16 helpers
// ---------------------------------------------------------------------------
__device__ __forceinline__ void cvt2(float x0, float x1, uint32_t& hp, uint32_t& lp) {
    // hp = {lo=bf16(x0), hi=bf16(x1)}; lp packs the residuals
    asm("cvt.rn.bf16x2.f32 %0, %1, %2;" : "=r"(hp) : "f"(x1), "f"(x0));
    float h0 = __uint_as_float(hp << 16);
    float h1 = __uint_as_float(hp & 0xFFFF0000u);
    asm("cvt.rn.bf16x2.f32 %0, %1, %2;" : "=r"(lp) : "f"(x1 - h1), "f"(x0 - h0));
}

__device__ __forceinline__ void mma_bf16(float* c, const uint32_t* a, const uint32_t* b) {
    asm volatile(
        "mma.sync.aligned.m16n8k16.row.col.f32.bf16.bf16.f32 "
        "{%0,%1,%2,%3}, {%4,%5,%6,%7}, {%8,%9}, {%0,%1,%2,%3};"
        : "+f"(c[0]), "+f"(c[1]), "+f"(c[2]), "+f"(c[3])
        : "r"(a[0]), "r"(a[1]), "r"(a[2]), "r"(a[3]), "r"(b[0]), "r"(b[1]));
}

// ---------------------------------------------------------------------------
// Fused attention kernels (bf16x3, flash-style, Q-tile resident).
// PASS 1: row sums of E=mask*exp(S/8) -> g_inv (no TT traffic).
// PASS 2: recompute S, W=E*inv written ONCE to wts, O += W*V chained in regs.
// 256 threads, warp grid 4(m) x 2(n-half): warp S tile 32m x 64n.
// ---------------------------------------------------------------------------
template <int PASS>
__global__ __launch_bounds__(256) void attn_kernel(
    const float* __restrict__ Qg, const float* __restrict__ Kg,
    const float* __restrict__ Vg, const int* __restrict__ mask,
    float* __restrict__ wts, float* __restrict__ invp, float* __restrict__ Og)
{
    extern __shared__ char smraw[];
    unsigned short* Qh = (unsigned short*)smraw;
    unsigned short* Ql = Qh + 128 * 72;
    unsigned short* Kh = Ql + 128 * 72;
    unsigned short* Kl = Kh + 128 * 72;
    unsigned short* Vh = Kl + 128 * 72;                 // pass2 only
    unsigned short* Vl = Vh + 64 * 136;
    float* mks = (PASS == 2) ? (float*)(Vl + 64 * 136) : (float*)Vh;  // 2048 floats
    float* rsc = mks + 2048;                            // pass1 rowsum scratch
    float* Osc = (float*)Vh;                            // pass2 O-reduce overlay

    const int tid = threadIdx.x, lane = tid & 31, wid = tid >> 5;
    const int g = lane >> 2, t4 = lane & 3;
    const int wm0 = (wid >> 1) * 32, wni = wid & 1;
    const int z = blockIdx.y, m0 = blockIdx.x * 128, gb = z >> 4;
    const long long zoff = (long long)z * (2048 * 64);
    const long long TT = 2048LL * 2048;

    for (int i = tid; i < 2048; i += 256)
        mks[i] = mask[gb * 2048 + i] ? 0.f : 1.f;

    // Q tile (128 x 64) -> SMEM hi/lo
#pragma unroll
    for (int i = 0; i < 8; ++i) {
        const int idx = tid + 256 * i, r = idx >> 4, q = idx & 15;
        float4 a = *(const float4*)(Qg + zoff + (long long)(m0 + r) * 64 + 4 * q);
        uint32_t h01, l01, h23, l23;
        cvt2(a.x, a.y, h01, l01);
        cvt2(a.z, a.w, h23, l23);
        *(uint2*)(Qh + r * 72 + 4 * q) = make_uint2(h01, h23);
        *(uint2*)(Ql + r * 72 + 4 * q) = make_uint2(l01, l23);
    }

    float iv[2][2];
    if (PASS == 2) {
#pragma unroll
        for (int mi = 0; mi < 2; ++mi) {
            iv[mi][0] = invp[z * 2048 + m0 + wm0 + 16 * mi + g];
            iv[mi][1] = invp[z * 2048 + m0 + wm0 + 16 * mi + g + 8];
        }
    }

    float oacc[2][8][4];
    float rs[2][2] = {{0.f, 0.f}, {0.f, 0.f}};
    if (PASS == 2) {
#pragma unroll
        for (int mi = 0; mi < 2; ++mi)
#pragma unroll
            for (int vf = 0; vf < 8; ++vf)
#pragma unroll
                for (int j = 0; j < 4; ++j) oacc[mi][vf][j] = 0.f;
    }

    __syncthreads();

    for (int nt = 0; nt < 16; ++nt) {
        // ---- gmem loads (coalesced float4 rows) ----
        float4 kR[8], vR[8];
#pragma unroll
        for (int i = 0; i < 8; ++i) {
            const int idx = tid + 256 * i, r = idx >> 4, q = idx & 15;
            kR[i] = *(const float4*)(Kg + zoff + (long long)(nt * 128 + r) * 64 + 4 * q);
            if (PASS == 2)
                vR[i] = *(const float4*)(Vg + zoff + (long long)(nt * 128 + r) * 64 + 4 * q);
        }
        if (nt) __syncthreads();          // prior compute done before overwrite
#pragma unroll
        for (int i = 0; i < 8; ++i) {
            const int idx = tid + 256 * i, r = idx >> 4, q = idx & 15;
            uint32_t h01, l01, h23, l23;
            cvt2(kR[i].x, kR[i].y, h01, l01);
            cvt2(kR[i].z, kR[i].w, h23, l23);
            *(uint2*)(Kh + r * 72 + 4 * q) = make_uint2(h01, h23);
            *(uint2*)(Kl + r * 72 + 4 * q) = make_uint2(l01, l23);
            if (PASS == 2) {
                uint32_t vh01, vl01, vh23, vl23;
                cvt2(vR[i].x, vR[i].y, vh01, vl01);
                cvt2(vR[i].z, vR[i].w, vh23, vl23);
                Vh[(4 * q + 0) * 136 + r] = (unsigned short)(vh01 & 0xFFFF);
                Vh[(4 * q + 1) * 136 + r] = (unsigned short)(vh01 >> 16);
                Vh[(4 * q + 2) * 136 + r] = (unsigned short)(vh23 & 0xFFFF);
                Vh[(4 * q + 3) * 136 + r] = (unsigned short)(vh23 >> 16);
                Vl[(4 * q + 0) * 136 + r] = (unsigned short)(vl01 & 0xFFFF);
                Vl[(4 * q + 1) * 136 + r] = (unsigned short)(vl01 >> 16);
                Vl[(4 * q + 2) * 136 + r] = (unsigned short)(vl23 & 0xFFFF);
                Vl[(4 * q + 3) * 136 + r] = (unsigned short)(vl23 >> 16);
            }
        }
        __syncthreads();

        // ---- S = Q K^T (bf16x3) ----
        float sacc[2][8][4];
#pragma unroll
        for (int mi = 0; mi < 2; ++mi)
#pragma unroll
            for (int nf = 0; nf < 8; ++nf)
#pragma unroll
                for (int j = 0; j < 4; ++j) sacc[mi][nf][j] = 0.f;

#pragma unroll
        for (int ks = 0; ks < 4; ++ks) {
            uint32_t ah[2][4], al[2][4];
#pragma unroll
            for (int mi = 0; mi < 2; ++mi) {
                const int ro = (wm0 + 16 * mi + g) * 72 + 16 * ks + 2 * t4;
                ah[mi][0] = *(const uint32_t*)(Qh + ro);
                ah[mi][1] = *(const uint32_t*)(Qh + ro + 8 * 72);
                ah[mi][2] = *(const uint32_t*)(Qh + ro + 8);
                ah[mi][3] = *(const uint32_t*)(Qh + ro + 8 * 72 + 8);
                al[mi][0] = *(const uint32_t*)(Ql + ro);
                al[mi][1] = *(const uint32_t*)(Ql + ro + 8 * 72);
                al[mi][2] = *(const uint32_t*)(Ql + ro + 8);
                al[mi][3] = *(const uint32_t*)(Ql + ro + 8 * 72 + 8);
            }
#pragma unroll
            for (int nf = 0; nf < 8; ++nf) {
                const int ro = (wni * 64 + 8 * nf + g) * 72 + 16 * ks + 2 * t4;
                uint32_t bh2[2], bl2[2];
                bh2[0] = *(const uint32_t*)(Kh + ro);
                bh2[1] = *(const uint32_t*)(Kh + ro + 8);
                bl2[0] = *(const uint32_t*)(Kl + ro);
                bl2[1] = *(const uint32_t*)(Kl + ro + 8);
#pragma unroll
                for (int mi = 0; mi < 2; ++mi) {
                    mma_bf16(sacc[mi][nf], ah[mi], bh2);
                    mma_bf16(sacc[mi][nf], ah[mi], bl2);
                    mma_bf16(sacc[mi][nf], al[mi], bh2);
                }
            }
        }

        if (PASS == 1) {
#pragma unroll
            for (int mi = 0; mi < 2; ++mi)
#pragma unroll
                for (int nf = 0; nf < 8; ++nf) {
                    const int n = nt * 128 + wni * 64 + 8 * nf + 2 * t4;
                    const float mk0 = mks[n], mk1 = mks[n + 1];
                    rs[mi][0] += mk0 * __expf(0.125f * sacc[mi][nf][0])
                               + mk1 * __expf(0.125f * sacc[mi][nf][1]);
                    rs[mi][1] += mk0 * __expf(0.125f * sacc[mi][nf][2])
                               + mk1 * __expf(0.125f * sacc[mi][nf][3]);
                }
        } else {
            // W = E*inv, write once, chain into O mma via register frags
#pragma unroll
            for (int kv = 0; kv < 4; ++kv) {
                uint32_t wh[2][4], wl[2][4];
#pragma unroll
                for (int mi = 0; mi < 2; ++mi) {
#pragma unroll
                    for (int j = 0; j < 2; ++j) {
                        const int nf = 2 * kv + j;
                        const int n = nt * 128 + wni * 64 + 8 * nf + 2 * t4;
                        const float mk0 = mks[n], mk1 = mks[n + 1];
                        const float w0 = mk0 * __expf(0.125f * sacc[mi][nf][0]) * iv[mi][0];
                        const float w1 = mk1 * __expf(0.125f * sacc[mi][nf][1]) * iv[mi][0];
                        const float w2 = mk0 * __expf(0.125f * sacc[mi][nf][2]) * iv[mi][1];
                        const float w3 = mk1 * __expf(0.125f * sacc[mi][nf][3]) * iv[mi][1];
                        const int r0 = m0 + wm0 + 16 * mi + g;
                        float* Wp = wts + (long long)z * TT + (long long)r0 * 2048 + n;
                        *(float2*)Wp = make_float2(w0, w1);
                        *(float2*)(Wp + 8LL * 2048) = make_float2(w2, w3);
                        uint32_t h01, l01, h23, l23;
                        cvt2(w0, w1, h01, l01);
                        cvt2(w2, w3, h23, l23);
                        wh[mi][2 * j]     = h01;
                        wh[mi][2 * j + 1] = h23;
                        wl[mi][2 * j]     = l01;
                        wl[mi][2 * j + 1] = l23;
                    }
                }
#pragma unroll
                for (int vf = 0; vf < 8; ++vf) {
                    const int ro = (8 * vf + g) * 136 + wni * 64 + 16 * kv + 2 * t4;
                    uint32_t bh2[2], bl2[2];
                    bh2[0] = *(const uint32_t*)(Vh + ro);
                    bh2[1] = *(const uint32_t*)(Vh + ro + 8);
                    bl2[0] = *(const uint32_t*)(Vl + ro);
                    bl2[1] = *(const uint32_t*)(Vl + ro + 8);
#pragma unroll
                    for (int mi = 0; mi < 2; ++mi) {
                        mma_bf16(oacc[mi][vf], wh[mi], bh2);
                        mma_bf16(oacc[mi][vf], wh[mi], bl2);
                        mma_bf16(oacc[mi][vf], wl[mi], bh2);
                    }
                }
            }
        }
    }

    if (PASS == 1) {
#pragma unroll
        for (int mi = 0; mi < 2; ++mi)
#pragma unroll
            for (int j = 0; j < 2; ++j) {
                float v = rs[mi][j];
                v += __shfl_xor_sync(0xffffffffu, v, 1);
                v += __shfl_xor_sync(0xffffffffu, v, 2);
                if (t4 == 0)
                    rsc[(wm0 + 16 * mi + g + 8 * j) * 2 + wni] = v;
            }
        __syncthreads();
        if (tid < 128) {
            const float s = rsc[tid * 2] + rsc[tid * 2 + 1];
            invp[z * 2048 + m0 + tid] = (s > 0.f) ? (1.f / s) : 0.f;
        }
    } else {
        __syncthreads();                  // done with V smem; overlay as scratch
        if (wni == 0) {
#pragma unroll
            for (int mi = 0; mi < 2; ++mi)
#pragma unroll
                for (int vf = 0; vf < 8; ++vf) {
                    const int r0 = wm0 + 16 * mi + g, c = 8 * vf + 2 * t4;
                    *(float2*)(Osc + r0 * 66 + c) = make_float2(oacc[mi][vf][0], oacc[mi][vf][1]);
                    *(float2*)(Osc + (r0 + 8) * 66 + c) = make_float2(oacc[mi][vf][2], oacc[mi][vf][3]);
                }
        }
        __syncthreads();
        if (wni == 1) {
#pragma unroll
            for (int mi = 0; mi < 2; ++mi)
#pragma unroll
                for (int vf = 0; vf < 8; ++vf) {
                    const int r0 = wm0 + 16 * mi + g, c = 8 * vf + 2 * t4;
                    float2 p0 = *(float2*)(Osc + r0 * 66 + c);
                    float2 p1 = *(float2*)(Osc + (r0 + 8) * 66 + c);
                    float* o0 = Og + ((long long)(gb * 2048 + m0 + r0)) * 1024 + (z & 15) * 64 + c;
                    float* o1 = Og + ((long long)(gb * 2048 + m0 + r0 + 8)) * 1024 + (z & 15) * 64 + c;
                    *(float2*)o0 = make_float2(p0.x + oacc[mi][vf][0], p0.y + oacc[mi][vf][1]);
                    *(float2*)o1 = make_float2(p1.x + oacc[mi][vf][2], p1.y + oacc[mi][vf][3]);
                }
        }
    }
}

// ---------------------------------------------------------------------------
// bf16x3 warp-MMA GEMM (round-4 proven).  C(128 x BN per CTA) = A(M,K)*B(N,K)^T
// EPI: 0=plain  1=QKV routing
// ---------------------------------------------------------------------------
template <int BN, int EPI>
__global__ __launch_bounds__(256) void gemm_mma(
    const float* __restrict__ A, long long lda,
    const float* __restrict__ B0, const float* __restrict__ B1, const float* __restrict__ B2,
    long long ldb,
    float* __restrict__ C, long long ldc, int Kd)
{
    constexpr int SAP = 40;
    constexpr int ASZ = 128 * SAP;
    constexpr int BSZ = BN * SAP;
    constexpr int STG = 2 * (ASZ + BSZ);
    constexpr int NF  = BN / 16;
    constexpr int NB4 = (BN * 8) / 256;

    extern __shared__ unsigned short smem[];

    const int tid = threadIdx.x, lane = tid & 31, wid = tid >> 5;
    const int g = lane >> 2, t4 = lane & 3;
    const int wm0 = (wid >> 1) * 32;
    const int wn0 = (wid & 1) * (BN / 2);
    const int m0 = blockIdx.y * 128, n0 = blockIdx.x * BN;

    const float* Ab = A;
    const float* Bb;
    if (EPI == 1) {
        const int mat = blockIdx.x >> 3;
        const float* Bs = (mat == 0) ? B0 : ((mat == 1) ? B1 : B2);
        Bb = Bs + (long long)((blockIdx.x & 7) * 128) * ldb;
    } else {
        Bb = B0 + (long long)n0 * ldb;
    }

    float acc[2][NF][4];
#pragma unroll
    for (int mi = 0; mi < 2; ++mi)
#pragma unroll
        for (int ni = 0; ni < NF; ++ni)
#pragma unroll
            for (int j = 0; j < 4; ++j) acc[mi][ni][j] = 0.f;

    float4 aR[4];
    float4 bR[NB4];

    auto loadA = [&](int s) {
        const int k0 = s << 5;
#pragma unroll
        for (int i = 0; i < 4; ++i) {
            const int idx = tid + 256 * i, r = idx >> 3, q = idx & 7;
            aR[i] = *(const float4*)(Ab + (long long)(m0 + r) * lda + (k0 + 4 * q));
        }
    };
    auto loadB = [&](int s) {
        const int k0 = s << 5;
#pragma unroll
        for (int i = 0; i < NB4; ++i) {
            const int idx = tid + 256 * i, r = idx >> 3, q = idx & 7;
            bR[i] = *(const float4*)(Bb + (long long)r * ldb + (k0 + 4 * q));
        }
    };
    auto stsA = [&](int st) {
        unsigned short* Ah = smem + st * STG;
        unsigned short* Al = Ah + ASZ;
#pragma unroll
        for (int i = 0; i < 4; ++i) {
            const int idx = tid + 256 * i, r = idx >> 3, q = idx & 7;
            uint32_t h01, l01, h23, l23;
            cvt2(aR[i].x, aR[i].y, h01, l01);
            cvt2(aR[i].z, aR[i].w, h23, l23);
            *(uint2*)(Ah + r * SAP + 4 * q) = make_uint2(h01, h23);
            *(uint2*)(Al + r * SAP + 4 * q) = make_uint2(l01, l23);
        }
    };
    auto stsB = [&](int st) {
        unsigned short* Bh = smem + st * STG + 2 * ASZ;
        unsigned short* Bl = Bh + BSZ;
#pragma unroll
        for (int i = 0; i < NB4; ++i) {
            const int idx = tid + 256 * i, r = idx >> 3, q = idx & 7;
            uint32_t h01, l01, h23, l23;
            cvt2(bR[i].x, bR[i].y, h01, l01);
            cvt2(bR[i].z, bR[i].w, h23, l23);
            *(uint2*)(Bh + r * SAP + 4 * q) = make_uint2(h01, h23);
            *(uint2*)(Bl + r * SAP + 4 * q) = make_uint2(l01, l23);
        }
    };
    auto compute = [&](int st) {
        const unsigned short* Ah = smem + st * STG;
        const unsigned short* Al = Ah + ASZ;
        const unsigned short* Bh = Ah + 2 * ASZ;
        const unsigned short* Bl = Bh + BSZ;
#pragma unroll
        for (int ks = 0; ks < 2; ++ks) {
            uint32_t ah[2][4], al[2][4], bh[NF][2], bl[NF][2];
#pragma unroll
            for (int mi = 0; mi < 2; ++mi) {
                const int ro = (wm0 + 16 * mi + g) * SAP + 16 * ks + 2 * t4;
                ah[mi][0] = *(const uint32_t*)(Ah + ro);
                ah[mi][1] = *(const uint32_t*)(Ah + ro + 8 * SAP);
                ah[mi][2] = *(const uint32_t*)(Ah + ro + 8);
                ah[mi][3] = *(const uint32_t*)(Ah + ro + 8 * SAP + 8);
                al[mi][0] = *(const uint32_t*)(Al + ro);
                al[mi][1] = *(const uint32_t*)(Al + ro + 8 * SAP);
                al[mi][2] = *(const uint32_t*)(Al + ro + 8);
                al[mi][3] = *(const uint32_t*)(Al + ro + 8 * SAP + 8);
            }
#pragma unroll
            for (int ni = 0; ni < NF; ++ni) {
                const int ro = (wn0 + 8 * ni + g) * SAP + 16 * ks + 2 * t4;
                bh[ni][0] = *(const uint32_t*)(Bh + ro);
                bh[ni][1] = *(const uint32_t*)(Bh + ro + 8);
                bl[ni][0] = *(const uint32_t*)(Bl + ro);
                bl[ni][1] = *(const uint32_t*)(Bl + ro + 8);
            }
#pragma unroll
            for (int mi = 0; mi < 2; ++mi)
#pragma unroll
                for (int ni = 0; ni < NF; ++ni) {
                    mma_bf16(acc[mi][ni], ah[mi], bh[ni]);
                    mma_bf16(acc[mi][ni], ah[mi], bl[ni]);
                    mma_bf16(acc[mi][ni], al[mi], bh[ni]);
                }
        }
    };

    const int nS = Kd >> 5;
    loadA(0); loadB(0);
    stsA(0);  stsB(0);
    __syncthreads();
    for (int s = 0; s < nS; ++s) {
        const int st = s & 1;
        if (s + 1 < nS) { loadA(s + 1); loadB(s + 1); }
        compute(st);
        __syncthreads();
        if (s + 1 < nS) { stsA(st ^ 1); stsB(st ^ 1); __syncthreads(); }
    }

#pragma unroll
    for (int mi = 0; mi < 2; ++mi) {
        const int r0 = wm0 + 16 * mi + g, r1 = r0 + 8;
#pragma unroll
        for (int ni = 0; ni < NF; ++ni) {
            const int c = wn0 + 8 * ni + 2 * t4;
            const float v0 = acc[mi][ni][0], v1 = acc[mi][ni][1];
            const float v2 = acc[mi][ni][2], v3 = acc[mi][ni][3];
            if (EPI == 0) {
                *(float2*)(C + (long long)(m0 + r0) * ldc + n0 + c) = make_float2(v0, v1);
                *(float2*)(C + (long long)(m0 + r1) * ldc + n0 + c) = make_float2(v2, v3);
            } else {
                const int nloc = (blockIdx.x & 7) * 128 + c;
                const int h = nloc >> 6, k = nloc & 63;
                const int mat = blockIdx.x >> 3;
                float* dst = (mat == 0) ? g_Q : ((mat == 1) ? g_K : g_V);
                const int mr0 = m0 + r0, b0 = mr0 >> 11, tt0 = mr0 & 2047;
                const int mr1 = m0 + r1, b1 = mr1 >> 11, tt1 = mr1 & 2047;
                *(float2*)(dst + ((long long)((b0 * 16 + h) * 2048 + tt0)) * 64 + k) = make_float2(v0, v1);
                *(float2*)(dst + ((long long)((b1 * 16 + h) * 2048 + tt1)) * 64 + k) = make_float2(v2, v3);
            }
        }
    }
}

// ---------------------------------------------------------------------------
// kernel_launch: x, mask(int32), W_Q, W_K, W_V, W_O -> d_out = [output | weights]
// ---------------------------------------------------------------------------
extern "C" void kernel_launch(void* const* d_in, const int* in_sizes, int n_in,
                              void* d_out, int out_size)
{
    const float* x    = (const float*)d_in[0];
    const int*   mask = (const int*)d_in[1];
    const float* WQ   = (const float*)d_in[2];
    const float* WK   = (const float*)d_in[3];
    const float* WV   = (const float*)d_in[4];
    const float* WO   = (const float*)d_in[5];

    float* out = (float*)d_out;
    float* wts = out + OUT_ELEMS;

    float *Qp, *Kp, *Vp, *Op, *invp;
    cudaGetSymbolAddress((void**)&Qp,   g_Q);
    cudaGetSymbolAddress((void**)&Kp,   g_K);
    cudaGetSymbolAddress((void**)&Vp,   g_V);
    cudaGetSymbolAddress((void**)&Op,   g_O);
    cudaGetSymbolAddress((void**)&invp, g_inv);

    const int SMG = 2 * 2 * (128 * 40 + 128 * 40) * 2;   // 81920 (gemm)
    const int SM1 = 4 * 128 * 72 * 2 + 8192 + 1024;      // 82944 (pass1)
    const int SM2 = 4 * 128 * 72 * 2 + 2 * 64 * 136 * 2 + 8192;  // 116736 (pass2)
    cudaFuncSetAttribute(gemm_mma<128, 1>, cudaFuncAttributeMaxDynamicSharedMemorySize, SMG);
    cudaFuncSetAttribute(gemm_mma<128, 0>, cudaFuncAttributeMaxDynamicSharedMemorySize, SMG);
    cudaFuncSetAttribute(attn_kernel<1>, cudaFuncAttributeMaxDynamicSharedMemorySize, SM1);
    cudaFuncSetAttribute(attn_kernel<2>, cudaFuncAttributeMaxDynamicSharedMemorySize, SM2);

    // 1) Fused QKV projection
    gemm_mma<128, 1><<<dim3(24, 32, 1), 256, SMG>>>(
        x, DMODEL, WQ, WK, WV, DMODEL, nullptr, 0, DMODEL);

    // 2) Pass 1: row sums -> inv (no TT traffic)
    attn_kernel<1><<<dim3(16, 32), 256, SM1>>>(Qp, Kp, Vp, mask, wts, invp, Op);

    // 3) Pass 2: W written once + O = W*V fused
    attn_kernel<2><<<dim3(16, 32), 256, SM2>>>(Qp, Kp, Vp, mask, wts, invp, Op);

    // 4) Output projection
    gemm_mma<128, 0><<<dim3(8, 32, 1), 256, SMG>>>(
        Op, DMODEL, WO, nullptr, nullptr, DMODEL, out, DMODEL, DMODEL);
}

// round 10
// speedup vs baseline: 2.7846x; 1.3250x over previous
#include <cuda_runtime.h>
#include <cstdint>

// ---------------------------------------------------------------------------
// Problem constants
// ---------------------------------------------------------------------------
#define DMODEL 1024
#define NHEADS 16
#define HD     64
#define BATCH  2
#define TSEQ   2048
#define BT     4096
#define NROWS  65536
#define OUT_ELEMS 4194304LL
#define QKV_ELEMS (32 * 2048 * 64)      // 4194304 elements per split array

// Scratch (static device memory; allocation APIs are forbidden)
__device__ unsigned short g_Qh[QKV_ELEMS];   // (z,t,64) bf16 hi
__device__ unsigned short g_Ql[QKV_ELEMS];   // lo
__device__ unsigned short g_Kh[QKV_ELEMS];
__device__ unsigned short g_Kl[QKV_ELEMS];
__device__ unsigned short g_Vth[QKV_ELEMS];  // (z,c,t) bf16 hi (V transposed)
__device__ unsigned short g_Vtl[QKV_ELEMS];
__device__ float g_O[BT * DMODEL];           // (B,T,H*64) fp32
__device__ float g_inv[NROWS];

// ---------------------------------------------------------------------------
// helpers
// ---------------------------------------------------------------------------
__device__ __forceinline__ uint32_t smem_u32(const void* p) {
    uint32_t a;
    asm("{ .reg .u64 t; cvta.to.shared.u64 t, %1; cvt.u32.u64 %0, t; }" : "=r"(a) : "l"(p));
    return a;
}
__device__ __forceinline__ void cvt2(float x0, float x1, uint32_t& hp, uint32_t& lp) {
    asm("cvt.rn.bf16x2.f32 %0, %1, %2;" : "=r"(hp) : "f"(x1), "f"(x0));
    float h0 = __uint_as_float(hp << 16);
    float h1 = __uint_as_float(hp & 0xFFFF0000u);
    asm("cvt.rn.bf16x2.f32 %0, %1, %2;" : "=r"(lp) : "f"(x1 - h1), "f"(x0 - h0));
}
__device__ __forceinline__ void mma_bf16(float* c, const uint32_t* a, const uint32_t* b) {
    asm volatile(
        "mma.sync.aligned.m16n8k16.row.col.f32.bf16.bf16.f32 "
        "{%0,%1,%2,%3}, {%4,%5,%6,%7}, {%8,%9}, {%0,%1,%2,%3};"
        : "+f"(c[0]), "+f"(c[1]), "+f"(c[2]), "+f"(c[3])
        : "r"(a[0]), "r"(a[1]), "r"(a[2]), "r"(a[3]), "r"(b[0]), "r"(b[1]));
}
__device__ __forceinline__ void ldsm4(uint32_t* r, uint32_t addr) {
    asm volatile("ldmatrix.sync.aligned.m8n8.x4.shared.b16 {%0,%1,%2,%3}, [%4];"
                 : "=r"(r[0]), "=r"(r[1]), "=r"(r[2]), "=r"(r[3]) : "r"(addr));
}
__device__ __forceinline__ void cpa(uint32_t d, const unsigned short* s) {
    asm volatile("cp.async.ca.shared.global [%0], [%1], 16;"
                 :: "r"(d), "l"(__cvta_generic_to_global(s)) : "memory");
}
#define CP_COMMIT() asm volatile("cp.async.commit_group;" ::: "memory")
#define CP_WAIT0()  asm volatile("cp.async.wait_group 0;" ::: "memory")
#define CP_WAIT1()  asm volatile("cp.async.wait_group 1;" ::: "memory")

// ---------------------------------------------------------------------------
// Attention passes (preconverted bf16 operands, cp.async, ldmatrix).
// PASS 1: single-term bf16 S; row sums of E -> g_inv.
// PASS 2: bf16x3 S; W=E*inv written ONCE to wts; O += W*V chained in regs.
// Grid (16 m-tiles, 32 z). 256 thr, warps 4(m) x 2(n). n-tile = 64.
// ---------------------------------------------------------------------------
template <int PASS>
__global__ __launch_bounds__(256) void attn_kernel(
    const unsigned short* __restrict__ Qhg, const unsigned short* __restrict__ Qlg,
    const unsigned short* __restrict__ Khg, const unsigned short* __restrict__ Klg,
    const unsigned short* __restrict__ Vhg, const unsigned short* __restrict__ Vlg,
    const int* __restrict__ mask, float* __restrict__ wts,
    float* __restrict__ invp, float* __restrict__ Og)
{
    extern __shared__ char smraw[];
    const uint32_t sb = smem_u32(smraw);
    constexpr uint32_t QH = 0;
    constexpr uint32_t QL = 18432;                               // pass2 only
    constexpr uint32_t KB = (PASS == 1) ? 18432u : 36864u;
    constexpr uint32_t KSTR = (PASS == 1) ? 9216u : 18432u;
    constexpr uint32_t VB = 73728;                               // pass2 only
    constexpr uint32_t MK = (PASS == 1) ? 36864u : 110592u;
    __shared__ float rsc[256];

    const int tid = threadIdx.x, lane = tid & 31, wid = tid >> 5;
    const int g = lane >> 2, t4 = lane & 3;
    const int wm0 = (wid >> 1) * 32, wni = wid & 1;
    const int z = blockIdx.y, m0 = blockIdx.x * 128, gb = z >> 4;
    const long long zo = (long long)z * (2048 * 64);
    const long long TT = 2048LL * 2048;

    unsigned char* mk8 = (unsigned char*)(smraw + MK);
    for (int i = tid; i < 2048; i += 256)
        mk8[i] = mask[gb * 2048 + i] ? 0 : 1;

    // ldmatrix lane-invariant address components
    const uint32_t aRow = (uint32_t)(lane & 15);
    const uint32_t aColB = (uint32_t)((lane >> 4) * 16);
    const uint32_t bRow = (uint32_t)(((lane >> 4) & 1) * 8 + (lane & 7));
    const uint32_t bColB = (uint32_t)(((lane >> 3) & 1) * 16);

    // ---- Q tile cp.async (group 0) ----
#pragma unroll
    for (int i = 0; i < 4; ++i) {
        const int idx = tid + 256 * i, r = idx >> 3, q = idx & 7;
        const long long so = zo + (long long)(m0 + r) * 64 + 8 * q;
        cpa(sb + QH + r * 144 + q * 16, Qhg + so);
        if (PASS == 2) cpa(sb + QL + r * 144 + q * 16, Qlg + so);
    }

    auto issueK = [&](int nt, int buf) {
        const uint32_t kb = sb + KB + (uint32_t)buf * KSTR;
#pragma unroll
        for (int i = 0; i < 2; ++i) {
            const int idx = tid + 256 * i, r = idx >> 3, q = idx & 7;
            const long long so = zo + (long long)(nt * 64 + r) * 64 + 8 * q;
            cpa(kb + r * 144 + q * 16, Khg + so);
            if (PASS == 2) cpa(kb + 9216 + r * 144 + q * 16, Klg + so);
        }
    };
    auto issueV = [&](int nt, int buf) {
        const uint32_t vb = sb + VB + (uint32_t)buf * 18432;
#pragma unroll
        for (int i = 0; i < 2; ++i) {
            const int idx = tid + 256 * i, c = idx >> 3, q = idx & 7;
            const long long so = (long long)(z * 64 + c) * 2048 + nt * 64 + 8 * q;
            cpa(vb + c * 144 + q * 16, Vhg + so);
            cpa(vb + 9216 + c * 144 + q * 16, Vlg + so);
        }
    };

    float iv[2][2];
    float oacc[2][8][4];
    float rs[2][2] = {{0.f, 0.f}, {0.f, 0.f}};
    if (PASS == 2) {
#pragma unroll
        for (int mi = 0; mi < 2; ++mi) {
            iv[mi][0] = invp[z * 2048 + m0 + wm0 + 16 * mi + g];
            iv[mi][1] = invp[z * 2048 + m0 + wm0 + 16 * mi + g + 8];
        }
#pragma unroll
        for (int mi = 0; mi < 2; ++mi)
#pragma unroll
            for (int cf = 0; cf < 8; ++cf)
#pragma unroll
                for (int j = 0; j < 4; ++j) oacc[mi][cf][j] = 0.f;
    }

    issueK(0, 0);
    if (PASS == 2) issueV(0, 0);
    CP_COMMIT();

    for (int nt = 0; nt < 32; ++nt) {
        const int buf = nt & 1;
        if (nt < 31) {
            issueK(nt + 1, buf ^ 1);
            if (PASS == 2) issueV(nt + 1, buf ^ 1);
            CP_COMMIT();
            CP_WAIT1();
        } else {
            CP_WAIT0();
        }
        __syncthreads();

        const uint32_t kh = sb + KB + (uint32_t)buf * KSTR;
        const uint32_t kl = kh + 9216;

        // ---- S = Q K^T ----
        float sacc[2][4][4];
#pragma unroll
        for (int mi = 0; mi < 2; ++mi)
#pragma unroll
            for (int nf = 0; nf < 4; ++nf)
#pragma unroll
                for (int j = 0; j < 4; ++j) sacc[mi][nf][j] = 0.f;

#pragma unroll
        for (int ks = 0; ks < 4; ++ks) {
            const uint32_t ac = (uint32_t)(ks * 32) + aColB;
            const uint32_t bc = (uint32_t)(ks * 32) + bColB;
            uint32_t a0h[4], a1h[4], b0h[4], b1h[4];
            ldsm4(a0h, sb + QH + (wm0 + aRow) * 144 + ac);
            ldsm4(a1h, sb + QH + (wm0 + 16 + aRow) * 144 + ac);
            ldsm4(b0h, kh + (wni * 32 + bRow) * 144 + bc);
            ldsm4(b1h, kh + (wni * 32 + 16 + bRow) * 144 + bc);
            mma_bf16(sacc[0][0], a0h, b0h); mma_bf16(sacc[0][1], a0h, b0h + 2);
            mma_bf16(sacc[0][2], a0h, b1h); mma_bf16(sacc[0][3], a0h, b1h + 2);
            mma_bf16(sacc[1][0], a1h, b0h); mma_bf16(sacc[1][1], a1h, b0h + 2);
            mma_bf16(sacc[1][2], a1h, b1h); mma_bf16(sacc[1][3], a1h, b1h + 2);
            if (PASS == 2) {
                uint32_t a0l[4], a1l[4], b0l[4], b1l[4];
                ldsm4(a0l, sb + QL + (wm0 + aRow) * 144 + ac);
                ldsm4(a1l, sb + QL + (wm0 + 16 + aRow) * 144 + ac);
                ldsm4(b0l, kl + (wni * 32 + bRow) * 144 + bc);
                ldsm4(b1l, kl + (wni * 32 + 16 + bRow) * 144 + bc);
                mma_bf16(sacc[0][0], a0h, b0l); mma_bf16(sacc[0][1], a0h, b0l + 2);
                mma_bf16(sacc[0][2], a0h, b1l); mma_bf16(sacc[0][3], a0h, b1l + 2);
                mma_bf16(sacc[1][0], a1h, b0l); mma_bf16(sacc[1][1], a1h, b0l + 2);
                mma_bf16(sacc[1][2], a1h, b1l); mma_bf16(sacc[1][3], a1h, b1l + 2);
                mma_bf16(sacc[0][0], a0l, b0h); mma_bf16(sacc[0][1], a0l, b0h + 2);
                mma_bf16(sacc[0][2], a0l, b1h); mma_bf16(sacc[0][3], a0l, b1h + 2);
                mma_bf16(sacc[1][0], a1l, b0h); mma_bf16(sacc[1][1], a1l, b0h + 2);
                mma_bf16(sacc[1][2], a1l, b1h); mma_bf16(sacc[1][3], a1l, b1h + 2);
            }
        }

        if (PASS == 1) {
#pragma unroll
            for (int mi = 0; mi < 2; ++mi)
#pragma unroll
                for (int nf = 0; nf < 4; ++nf) {
                    const int n = nt * 64 + wni * 32 + 8 * nf + 2 * t4;
                    const float f0 = (float)mk8[n], f1 = (float)mk8[n + 1];
                    rs[mi][0] += f0 * __expf(0.125f * sacc[mi][nf][0])
                               + f1 * __expf(0.125f * sacc[mi][nf][1]);
                    rs[mi][1] += f0 * __expf(0.125f * sacc[mi][nf][2])
                               + f1 * __expf(0.125f * sacc[mi][nf][3]);
                }
        } else {
            const uint32_t vh = sb + VB + (uint32_t)buf * 18432;
            const uint32_t vl = vh + 9216;
#pragma unroll
            for (int kv = 0; kv < 2; ++kv) {
                uint32_t wh[2][4], wl[2][4];
#pragma unroll
                for (int mi = 0; mi < 2; ++mi) {
#pragma unroll
                    for (int j = 0; j < 2; ++j) {
                        const int nf = 2 * kv + j;
                        const int n = nt * 64 + wni * 32 + 8 * nf + 2 * t4;
                        const float f0 = (float)mk8[n], f1 = (float)mk8[n + 1];
                        const float w0 = f0 * __expf(0.125f * sacc[mi][nf][0]) * iv[mi][0];
                        const float w1 = f1 * __expf(0.125f * sacc[mi][nf][1]) * iv[mi][0];
                        const float w2 = f0 * __expf(0.125f * sacc[mi][nf][2]) * iv[mi][1];
                        const float w3 = f1 * __expf(0.125f * sacc[mi][nf][3]) * iv[mi][1];
                        const int r0 = m0 + wm0 + 16 * mi + g;
                        float* Wp = wts + (long long)z * TT + (long long)r0 * 2048 + n;
                        *(float2*)Wp = make_float2(w0, w1);
                        *(float2*)(Wp + 8LL * 2048) = make_float2(w2, w3);
                        cvt2(w0, w1, wh[mi][2 * j], wl[mi][2 * j]);
                        cvt2(w2, w3, wh[mi][2 * j + 1], wl[mi][2 * j + 1]);
                    }
                }
                const uint32_t vcb = (uint32_t)(wni * 64 + kv * 32) + bColB;
#pragma unroll
                for (int cfp = 0; cfp < 4; ++cfp) {
                    uint32_t vh4[4], vl4[4];
                    ldsm4(vh4, vh + (cfp * 16 + bRow) * 144 + vcb);
                    ldsm4(vl4, vl + (cfp * 16 + bRow) * 144 + vcb);
#pragma unroll
                    for (int mi = 0; mi < 2; ++mi)
#pragma unroll
                        for (int j = 0; j < 2; ++j) {
                            float* o = oacc[mi][2 * cfp + j];
                            mma_bf16(o, wh[mi], vh4 + 2 * j);
                            mma_bf16(o, wh[mi], vl4 + 2 * j);
                            mma_bf16(o, wl[mi], vh4 + 2 * j);
                        }
                }
            }
        }
        __syncthreads();
    }

    if (PASS == 1) {
#pragma unroll
        for (int mi = 0; mi < 2; ++mi)
#pragma unroll
            for (int j = 0; j < 2; ++j) {
                float v = rs[mi][j];
                v += __shfl_xor_sync(0xffffffffu, v, 1);
                v += __shfl_xor_sync(0xffffffffu, v, 2);
                if (t4 == 0) rsc[(wm0 + 16 * mi + g + 8 * j) * 2 + wni] = v;
            }
        __syncthreads();
        if (tid < 128) {
            const float s = rsc[tid * 2] + rsc[tid * 2 + 1];
            invp[z * 2048 + m0 + tid] = (s > 0.f) ? (1.f / s) : 0.f;
        }
    } else {
        float* Osc = (float*)(smraw + 36864);   // overlay on K buffers
        if (wni == 0) {
#pragma unroll
            for (int mi = 0; mi < 2; ++mi)
#pragma unroll
                for (int cf = 0; cf < 8; ++cf) {
                    const int r0 = wm0 + 16 * mi + g, c = 8 * cf + 2 * t4;
                    *(float2*)(Osc + r0 * 66 + c) = make_float2(oacc[mi][cf][0], oacc[mi][cf][1]);
                    *(float2*)(Osc + (r0 + 8) * 66 + c) = make_float2(oacc[mi][cf][2], oacc[mi][cf][3]);
                }
        }
        __syncthreads();
        if (wni == 1) {
#pragma unroll
            for (int mi = 0; mi < 2; ++mi)
#pragma unroll
                for (int cf = 0; cf < 8; ++cf) {
                    const int r0 = wm0 + 16 * mi + g, c = 8 * cf + 2 * t4;
                    float2 p0 = *(float2*)(Osc + r0 * 66 + c);
                    float2 p1 = *(float2*)(Osc + (r0 + 8) * 66 + c);
                    float* o0 = Og + ((long long)(gb * 2048 + m0 + r0)) * 1024 + (z & 15) * 64 + c;
                    float* o1 = Og + ((long long)(gb * 2048 + m0 + r0 + 8)) * 1024 + (z & 15) * 64 + c;
                    *(float2*)o0 = make_float2(p0.x + oacc[mi][cf][0], p0.y + oacc[mi][cf][1]);
                    *(float2*)o1 = make_float2(p1.x + oacc[mi][cf][2], p1.y + oacc[mi][cf][3]);
                }
        }
    }
}

// ---------------------------------------------------------------------------
// bf16x3 warp-MMA GEMM.  C(128 x 128 per CTA) = A(M,K) * B(N,K)^T
// EPI 0: plain fp32 store (out-proj).  EPI 1: QKV routing -> bf16 split arrays.
// ---------------------------------------------------------------------------
template <int BN, int EPI>
__global__ __launch_bounds__(256) void gemm_mma(
    const float* __restrict__ A, long long lda,
    const float* __restrict__ B0, const float* __restrict__ B1, const float* __restrict__ B2,
    long long ldb,
    float* __restrict__ C, long long ldc, int Kd)
{
    constexpr int SAP = 40;
    constexpr int ASZ = 128 * SAP;
    constexpr int BSZ = BN * SAP;
    constexpr int STG = 2 * (ASZ + BSZ);
    constexpr int NF  = BN / 16;
    constexpr int NB4 = (BN * 8) / 256;

    extern __shared__ unsigned short smem[];
    const uint32_t smB = smem_u32(smem);

    const int tid = threadIdx.x, lane = tid & 31, wid = tid >> 5;
    const int g = lane >> 2, t4 = lane & 3;
    const int wm0 = (wid >> 1) * 32;
    const int wn0 = (wid & 1) * (BN / 2);
    const int m0 = blockIdx.y * 128, n0 = blockIdx.x * BN;

    const uint32_t aRow = (uint32_t)(lane & 15);
    const uint32_t aColB = (uint32_t)((lane >> 4) * 16);
    const uint32_t bRow = (uint32_t)(((lane >> 4) & 1) * 8 + (lane & 7));
    const uint32_t bColB = (uint32_t)(((lane >> 3) & 1) * 16);

    const float* Ab = A;
    const float* Bb;
    if (EPI == 1) {
        const int mat = blockIdx.x >> 3;
        const float* Bs = (mat == 0) ? B0 : ((mat == 1) ? B1 : B2);
        Bb = Bs + (long long)((blockIdx.x & 7) * 128) * ldb;
    } else {
        Bb = B0 + (long long)n0 * ldb;
    }

    float acc[2][NF][4];
#pragma unroll
    for (int mi = 0; mi < 2; ++mi)
#pragma unroll
        for (int ni = 0; ni < NF; ++ni)
#pragma unroll
            for (int j = 0; j < 4; ++j) acc[mi][ni][j] = 0.f;

    float4 aR[4];
    float4 bR[NB4];

    auto loadA = [&](int s) {
        const int k0 = s << 5;
#pragma unroll
        for (int i = 0; i < 4; ++i) {
            const int idx = tid + 256 * i, r = idx >> 3, q = idx & 7;
            aR[i] = *(const float4*)(Ab + (long long)(m0 + r) * lda + (k0 + 4 * q));
        }
    };
    auto loadB = [&](int s) {
        const int k0 = s << 5;
#pragma unroll
        for (int i = 0; i < NB4; ++i) {
            const int idx = tid + 256 * i, r = idx >> 3, q = idx & 7;
            bR[i] = *(const float4*)(Bb + (long long)r * ldb + (k0 + 4 * q));
        }
    };
    auto stsA = [&](int st) {
        unsigned short* Ah = smem + st * STG;
        unsigned short* Al = Ah + ASZ;
#pragma unroll
        for (int i = 0; i < 4; ++i) {
            const int idx = tid + 256 * i, r = idx >> 3, q = idx & 7;
            uint32_t h01, l01, h23, l23;
            cvt2(aR[i].x, aR[i].y, h01, l01);
            cvt2(aR[i].z, aR[i].w, h23, l23);
            *(uint2*)(Ah + r * SAP + 4 * q) = make_uint2(h01, h23);
            *(uint2*)(Al + r * SAP + 4 * q) = make_uint2(l01, l23);
        }
    };
    auto stsB = [&](int st) {
        unsigned short* Bh = smem + st * STG + 2 * ASZ;
        unsigned short* Bl = Bh + BSZ;
#pragma unroll
        for (int i = 0; i < NB4; ++i) {
            const int idx = tid + 256 * i, r = idx >> 3, q = idx & 7;
            uint32_t h01, l01, h23, l23;
            cvt2(bR[i].x, bR[i].y, h01, l01);
            cvt2(bR[i].z, bR[i].w, h23, l23);
            *(uint2*)(Bh + r * SAP + 4 * q) = make_uint2(h01, h23);
            *(uint2*)(Bl + r * SAP + 4 * q) = make_uint2(l01, l23);
        }
    };
    auto compute = [&](int st) {
        const uint32_t AhB = smB + (uint32_t)(st * STG) * 2;
        const uint32_t AlB = AhB + ASZ * 2;
        const uint32_t BhB = AhB + 2 * ASZ * 2;
        const uint32_t BlB = BhB + BSZ * 2;
#pragma unroll
        for (int ks = 0; ks < 2; ++ks) {
            const uint32_t ac = (uint32_t)(ks * 32) + aColB;
            const uint32_t bc = (uint32_t)(ks * 32) + bColB;
            uint32_t ah[2][4], al[2][4];
#pragma unroll
            for (int mi = 0; mi < 2; ++mi) {
                ldsm4(ah[mi], AhB + (wm0 + 16 * mi + aRow) * 80 + ac);
                ldsm4(al[mi], AlB + (wm0 + 16 * mi + aRow) * 80 + ac);
            }
#pragma unroll
            for (int nfp = 0; nfp < NF / 2; ++nfp) {
                uint32_t bh4[4], bl4[4];
                ldsm4(bh4, BhB + (wn0 + nfp * 16 + bRow) * 80 + bc);
                ldsm4(bl4, BlB + (wn0 + nfp * 16 + bRow) * 80 + bc);
#pragma unroll
                for (int mi = 0; mi < 2; ++mi)
#pragma unroll
                    for (int j = 0; j < 2; ++j) {
                        float* o = acc[mi][2 * nfp + j];
                        mma_bf16(o, ah[mi], bh4 + 2 * j);
                        mma_bf16(o, ah[mi], bl4 + 2 * j);
                        mma_bf16(o, al[mi], bh4 + 2 * j);
                    }
            }
        }
    };

    const int nS = Kd >> 5;
    loadA(0); loadB(0);
    stsA(0);  stsB(0);
    __syncthreads();
    for (int s = 0; s < nS; ++s) {
        const int st = s & 1;
        if (s + 1 < nS) { loadA(s + 1); loadB(s + 1); }
        compute(st);
        __syncthreads();
        if (s + 1 < nS) { stsA(st ^ 1); stsB(st ^ 1); __syncthreads(); }
    }

#pragma unroll
    for (int mi = 0; mi < 2; ++mi) {
        const int r0 = wm0 + 16 * mi + g, r1 = r0 + 8;
#pragma unroll
        for (int ni = 0; ni < NF; ++ni) {
            const int c = wn0 + 8 * ni + 2 * t4;
            const float v0 = acc[mi][ni][0], v1 = acc[mi][ni][1];
            const float v2 = acc[mi][ni][2], v3 = acc[mi][ni][3];
            if (EPI == 0) {
                *(float2*)(C + (long long)(m0 + r0) * ldc + n0 + c) = make_float2(v0, v1);
                *(float2*)(C + (long long)(m0 + r1) * ldc + n0 + c) = make_float2(v2, v3);
            } else {
                const int nloc = (blockIdx.x & 7) * 128 + c;
                const int h = nloc >> 6, k = nloc & 63;
                const int mat = blockIdx.x >> 3;
                const int mr0 = m0 + r0, b0 = mr0 >> 11, tt0 = mr0 & 2047;
                const int mr1 = m0 + r1, b1 = mr1 >> 11, tt1 = mr1 & 2047;
                uint32_t h01, l01, h23, l23;
                cvt2(v0, v1, h01, l01);
                cvt2(v2, v3, h23, l23);
                if (mat < 2) {
                    unsigned short* dh = (mat == 0) ? g_Qh : g_Kh;
                    unsigned short* dl = (mat == 0) ? g_Ql : g_Kl;
                    const long long o0 = ((long long)((b0 * 16 + h) * 2048 + tt0)) * 64 + k;
                    const long long o1 = ((long long)((b1 * 16 + h) * 2048 + tt1)) * 64 + k;
                    *(uint32_t*)&dh[o0] = h01; *(uint32_t*)&dl[o0] = l01;
                    *(uint32_t*)&dh[o1] = h23; *(uint32_t*)&dl[o1] = l23;
                } else {
                    const long long c0 = ((long long)((b0 * 16 + h) * 64 + k)) * 2048;
                    const long long c1 = c0 + 2048;
                    g_Vth[c0 + tt0] = (unsigned short)(h01 & 0xFFFF);
                    g_Vth[c1 + tt0] = (unsigned short)(h01 >> 16);
                    g_Vtl[c0 + tt0] = (unsigned short)(l01 & 0xFFFF);
                    g_Vtl[c1 + tt0] = (unsigned short)(l01 >> 16);
                    g_Vth[c0 + tt1] = (unsigned short)(h23 & 0xFFFF);
                    g_Vth[c1 + tt1] = (unsigned short)(h23 >> 16);
                    g_Vtl[c0 + tt1] = (unsigned short)(l23 & 0xFFFF);
                    g_Vtl[c1 + tt1] = (unsigned short)(l23 >> 16);
                }
            }
        }
    }
}

// ---------------------------------------------------------------------------
// kernel_launch: x, mask(int32), W_Q, W_K, W_V, W_O -> d_out = [output | weights]
// ---------------------------------------------------------------------------
extern "C" void kernel_launch(void* const* d_in, const int* in_sizes, int n_in,
                              void* d_out, int out_size)
{
    const float* x    = (const float*)d_in[0];
    const int*   mask = (const int*)d_in[1];
    const float* WQ   = (const float*)d_in[2];
    const float* WK   = (const float*)d_in[3];
    const float* WV   = (const float*)d_in[4];
    const float* WO   = (const float*)d_in[5];

    float* out = (float*)d_out;
    float* wts = out + OUT_ELEMS;

    unsigned short *Qh, *Ql, *Kh, *Kl, *Vth, *Vtl;
    float *Op, *invp;
    cudaGetSymbolAddress((void**)&Qh,  g_Qh);
    cudaGetSymbolAddress((void**)&Ql,  g_Ql);
    cudaGetSymbolAddress((void**)&Kh,  g_Kh);
    cudaGetSymbolAddress((void**)&Kl,  g_Kl);
    cudaGetSymbolAddress((void**)&Vth, g_Vth);
    cudaGetSymbolAddress((void**)&Vtl, g_Vtl);
    cudaGetSymbolAddress((void**)&Op,  g_O);
    cudaGetSymbolAddress((void**)&invp, g_inv);

    const int SMG = 2 * 2 * (128 * 40 + 128 * 40) * 2;   // 81920
    const int SM1 = 38912;
    const int SM2 = 112640;
    cudaFuncSetAttribute(gemm_mma<128, 1>, cudaFuncAttributeMaxDynamicSharedMemorySize, SMG);
    cudaFuncSetAttribute(gemm_mma<128, 0>, cudaFuncAttributeMaxDynamicSharedMemorySize, SMG);
    cudaFuncSetAttribute(attn_kernel<1>, cudaFuncAttributeMaxDynamicSharedMemorySize, SM1);
    cudaFuncSetAttribute(attn_kernel<2>, cudaFuncAttributeMaxDynamicSharedMemorySize, SM2);

    // 1) Fused QKV projection -> bf16 split Q,K and transposed V
    gemm_mma<128, 1><<<dim3(24, 32, 1), 256, SMG>>>(
        x, DMODEL, WQ, WK, WV, DMODEL, nullptr, 0, DMODEL);

    // 2) Pass 1: row sums -> inv (single-term bf16 S, zero TT traffic)
    attn_kernel<1><<<dim3(16, 32), 256, SM1>>>(
        Qh, Ql, Kh, Kl, Vth, Vtl, mask, wts, invp, Op);

    // 3) Pass 2: W written once + O = W*V fused (bf16x3)
    attn_kernel<2><<<dim3(16, 32), 256, SM2>>>(
        Qh, Ql, Kh, Kl, Vth, Vtl, mask, wts, invp, Op);

    // 4) Output projection
    gemm_mma<128, 0><<<dim3(8, 32, 1), 256, SMG>>>(
        Op, DMODEL, WO, nullptr, nullptr, DMODEL, out, DMODEL, DMODEL);
}

// round 11
// speedup vs baseline: 2.8512x; 1.0239x over previous
#include <cuda_runtime.h>
#include <cstdint>

// ---------------------------------------------------------------------------
// Problem constants
// ---------------------------------------------------------------------------
#define DMODEL 1024
#define NHEADS 16
#define HD     64
#define BATCH  2
#define TSEQ   2048
#define BT     4096
#define NROWS  65536
#define OUT_ELEMS 4194304LL
#define QKV_ELEMS (32 * 2048 * 64)      // 4194304 elements per split array

// Scratch (static device memory; allocation APIs are forbidden)
__device__ unsigned short g_Qh[QKV_ELEMS];   // (z,t,64) bf16 hi
__device__ unsigned short g_Ql[QKV_ELEMS];   // lo
__device__ unsigned short g_Kh[QKV_ELEMS];
__device__ unsigned short g_Kl[QKV_ELEMS];
__device__ unsigned short g_Vth[QKV_ELEMS];  // (z,c,t) bf16 hi (V transposed)
__device__ unsigned short g_Vtl[QKV_ELEMS];
__device__ float g_O[BT * DMODEL];           // (B,T,H*64) fp32
__device__ float g_inv[NROWS];

// ---------------------------------------------------------------------------
// helpers
// ---------------------------------------------------------------------------
__device__ __forceinline__ uint32_t smem_u32(const void* p) {
    uint32_t a;
    asm("{ .reg .u64 t; cvta.to.shared.u64 t, %1; cvt.u32.u64 %0, t; }" : "=r"(a) : "l"(p));
    return a;
}
__device__ __forceinline__ void cvt2(float x0, float x1, uint32_t& hp, uint32_t& lp) {
    asm("cvt.rn.bf16x2.f32 %0, %1, %2;" : "=r"(hp) : "f"(x1), "f"(x0));
    float h0 = __uint_as_float(hp << 16);
    float h1 = __uint_as_float(hp & 0xFFFF0000u);
    asm("cvt.rn.bf16x2.f32 %0, %1, %2;" : "=r"(lp) : "f"(x1 - h1), "f"(x0 - h0));
}
__device__ __forceinline__ void mma_bf16(float* c, const uint32_t* a, const uint32_t* b) {
    asm volatile(
        "mma.sync.aligned.m16n8k16.row.col.f32.bf16.bf16.f32 "
        "{%0,%1,%2,%3}, {%4,%5,%6,%7}, {%8,%9}, {%0,%1,%2,%3};"
        : "+f"(c[0]), "+f"(c[1]), "+f"(c[2]), "+f"(c[3])
        : "r"(a[0]), "r"(a[1]), "r"(a[2]), "r"(a[3]), "r"(b[0]), "r"(b[1]));
}
__device__ __forceinline__ void ldsm4(uint32_t* r, uint32_t addr) {
    asm volatile("ldmatrix.sync.aligned.m8n8.x4.shared.b16 {%0,%1,%2,%3}, [%4];"
                 : "=r"(r[0]), "=r"(r[1]), "=r"(r[2]), "=r"(r[3]) : "r"(addr));
}
__device__ __forceinline__ void cpa(uint32_t d, const unsigned short* s) {
    asm volatile("cp.async.ca.shared.global [%0], [%1], 16;"
                 :: "r"(d), "l"(__cvta_generic_to_global(s)) : "memory");
}
#define CP_COMMIT() asm volatile("cp.async.commit_group;" ::: "memory")
#define CP_WAIT0()  asm volatile("cp.async.wait_group 0;" ::: "memory")
#define CP_WAIT1()  asm volatile("cp.async.wait_group 1;" ::: "memory")

// ---------------------------------------------------------------------------
// Attention passes (preconverted bf16 operands, cp.async, ldmatrix).
// PASS 1: single-term bf16 S; row sums of E -> g_inv.
// PASS 2: bf16x3 S; W=E*inv written ONCE to wts; O += W*V chained in regs.
// Grid (16 m-tiles, 32 z). 256 thr, warps 4(m) x 2(n). n-tile = 64.
// (unchanged from round 10 — proven)
// ---------------------------------------------------------------------------
template <int PASS>
__global__ __launch_bounds__(256) void attn_kernel(
    const unsigned short* __restrict__ Qhg, const unsigned short* __restrict__ Qlg,
    const unsigned short* __restrict__ Khg, const unsigned short* __restrict__ Klg,
    const unsigned short* __restrict__ Vhg, const unsigned short* __restrict__ Vlg,
    const int* __restrict__ mask, float* __restrict__ wts,
    float* __restrict__ invp, float* __restrict__ Og)
{
    extern __shared__ char smraw[];
    const uint32_t sb = smem_u32(smraw);
    constexpr uint32_t QH = 0;
    constexpr uint32_t QL = 18432;                               // pass2 only
    constexpr uint32_t KB = (PASS == 1) ? 18432u : 36864u;
    constexpr uint32_t KSTR = (PASS == 1) ? 9216u : 18432u;
    constexpr uint32_t VB = 73728;                               // pass2 only
    constexpr uint32_t MK = (PASS == 1) ? 36864u : 110592u;
    __shared__ float rsc[256];

    const int tid = threadIdx.x, lane = tid & 31, wid = tid >> 5;
    const int g = lane >> 2, t4 = lane & 3;
    const int wm0 = (wid >> 1) * 32, wni = wid & 1;
    const int z = blockIdx.y, m0 = blockIdx.x * 128, gb = z >> 4;
    const long long zo = (long long)z * (2048 * 64);
    const long long TT = 2048LL * 2048;

    unsigned char* mk8 = (unsigned char*)(smraw + MK);
    for (int i = tid; i < 2048; i += 256)
        mk8[i] = mask[gb * 2048 + i] ? 0 : 1;

    const uint32_t aRow = (uint32_t)(lane & 15);
    const uint32_t aColB = (uint32_t)((lane >> 4) * 16);
    const uint32_t bRow = (uint32_t)(((lane >> 4) & 1) * 8 + (lane & 7));
    const uint32_t bColB = (uint32_t)(((lane >> 3) & 1) * 16);

#pragma unroll
    for (int i = 0; i < 4; ++i) {
        const int idx = tid + 256 * i, r = idx >> 3, q = idx & 7;
        const long long so = zo + (long long)(m0 + r) * 64 + 8 * q;
        cpa(sb + QH + r * 144 + q * 16, Qhg + so);
        if (PASS == 2) cpa(sb + QL + r * 144 + q * 16, Qlg + so);
    }

    auto issueK = [&](int nt, int buf) {
        const uint32_t kb = sb + KB + (uint32_t)buf * KSTR;
#pragma unroll
        for (int i = 0; i < 2; ++i) {
            const int idx = tid + 256 * i, r = idx >> 3, q = idx & 7;
            const long long so = zo + (long long)(nt * 64 + r) * 64 + 8 * q;
            cpa(kb + r * 144 + q * 16, Khg + so);
            if (PASS == 2) cpa(kb + 9216 + r * 144 + q * 16, Klg + so);
        }
    };
    auto issueV = [&](int nt, int buf) {
        const uint32_t vb = sb + VB + (uint32_t)buf * 18432;
#pragma unroll
        for (int i = 0; i < 2; ++i) {
            const int idx = tid + 256 * i, c = idx >> 3, q = idx & 7;
            const long long so = (long long)(z * 64 + c) * 2048 + nt * 64 + 8 * q;
            cpa(vb + c * 144 + q * 16, Vhg + so);
            cpa(vb + 9216 + c * 144 + q * 16, Vlg + so);
        }
    };

    float iv[2][2];
    float oacc[2][8][4];
    float rs[2][2] = {{0.f, 0.f}, {0.f, 0.f}};
    if (PASS == 2) {
#pragma unroll
        for (int mi = 0; mi < 2; ++mi) {
            iv[mi][0] = invp[z * 2048 + m0 + wm0 + 16 * mi + g];
            iv[mi][1] = invp[z * 2048 + m0 + wm0 + 16 * mi + g + 8];
        }
#pragma unroll
        for (int mi = 0; mi < 2; ++mi)
#pragma unroll
            for (int cf = 0; cf < 8; ++cf)
#pragma unroll
                for (int j = 0; j < 4; ++j) oacc[mi][cf][j] = 0.f;
    }

    issueK(0, 0);
    if (PASS == 2) issueV(0, 0);
    CP_COMMIT();

    for (int nt = 0; nt < 32; ++nt) {
        const int buf = nt & 1;
        if (nt < 31) {
            issueK(nt + 1, buf ^ 1);
            if (PASS == 2) issueV(nt + 1, buf ^ 1);
            CP_COMMIT();
            CP_WAIT1();
        } else {
            CP_WAIT0();
        }
        __syncthreads();

        const uint32_t kh = sb + KB + (uint32_t)buf * KSTR;
        const uint32_t kl = kh + 9216;

        float sacc[2][4][4];
#pragma unroll
        for (int mi = 0; mi < 2; ++mi)
#pragma unroll
            for (int nf = 0; nf < 4; ++nf)
#pragma unroll
                for (int j = 0; j < 4; ++j) sacc[mi][nf][j] = 0.f;

#pragma unroll
        for (int ks = 0; ks < 4; ++ks) {
            const uint32_t ac = (uint32_t)(ks * 32) + aColB;
            const uint32_t bc = (uint32_t)(ks * 32) + bColB;
            uint32_t a0h[4], a1h[4], b0h[4], b1h[4];
            ldsm4(a0h, sb + QH + (wm0 + aRow) * 144 + ac);
            ldsm4(a1h, sb + QH + (wm0 + 16 + aRow) * 144 + ac);
            ldsm4(b0h, kh + (wni * 32 + bRow) * 144 + bc);
            ldsm4(b1h, kh + (wni * 32 + 16 + bRow) * 144 + bc);
            mma_bf16(sacc[0][0], a0h, b0h); mma_bf16(sacc[0][1], a0h, b0h + 2);
            mma_bf16(sacc[0][2], a0h, b1h); mma_bf16(sacc[0][3], a0h, b1h + 2);
            mma_bf16(sacc[1][0], a1h, b0h); mma_bf16(sacc[1][1], a1h, b0h + 2);
            mma_bf16(sacc[1][2], a1h, b1h); mma_bf16(sacc[1][3], a1h, b1h + 2);
            if (PASS == 2) {
                uint32_t a0l[4], a1l[4], b0l[4], b1l[4];
                ldsm4(a0l, sb + QL + (wm0 + aRow) * 144 + ac);
                ldsm4(a1l, sb + QL + (wm0 + 16 + aRow) * 144 + ac);
                ldsm4(b0l, kl + (wni * 32 + bRow) * 144 + bc);
                ldsm4(b1l, kl + (wni * 32 + 16 + bRow) * 144 + bc);
                mma_bf16(sacc[0][0], a0h, b0l); mma_bf16(sacc[0][1], a0h, b0l + 2);
                mma_bf16(sacc[0][2], a0h, b1l); mma_bf16(sacc[0][3], a0h, b1l + 2);
                mma_bf16(sacc[1][0], a1h, b0l); mma_bf16(sacc[1][1], a1h, b0l + 2);
                mma_bf16(sacc[1][2], a1h, b1l); mma_bf16(sacc[1][3], a1h, b1l + 2);
                mma_bf16(sacc[0][0], a0l, b0h); mma_bf16(sacc[0][1], a0l, b0h + 2);
                mma_bf16(sacc[0][2], a0l, b1h); mma_bf16(sacc[0][3], a0l, b1h + 2);
                mma_bf16(sacc[1][0], a1l, b0h); mma_bf16(sacc[1][1], a1l, b0h + 2);
                mma_bf16(sacc[1][2], a1l, b1h); mma_bf16(sacc[1][3], a1l, b1h + 2);
            }
        }

        if (PASS == 1) {
#pragma unroll
            for (int mi = 0; mi < 2; ++mi)
#pragma unroll
                for (int nf = 0; nf < 4; ++nf) {
                    const int n = nt * 64 + wni * 32 + 8 * nf + 2 * t4;
                    const float f0 = (float)mk8[n], f1 = (float)mk8[n + 1];
                    rs[mi][0] += f0 * __expf(0.125f * sacc[mi][nf][0])
                               + f1 * __expf(0.125f * sacc[mi][nf][1]);
                    rs[mi][1] += f0 * __expf(0.125f * sacc[mi][nf][2])
                               + f1 * __expf(0.125f * sacc[mi][nf][3]);
                }
        } else {
            const uint32_t vh = sb + VB + (uint32_t)buf * 18432;
            const uint32_t vl = vh + 9216;
#pragma unroll
            for (int kv = 0; kv < 2; ++kv) {
                uint32_t wh[2][4], wl[2][4];
#pragma unroll
                for (int mi = 0; mi < 2; ++mi) {
#pragma unroll
                    for (int j = 0; j < 2; ++j) {
                        const int nf = 2 * kv + j;
                        const int n = nt * 64 + wni * 32 + 8 * nf + 2 * t4;
                        const float f0 = (float)mk8[n], f1 = (float)mk8[n + 1];
                        const float w0 = f0 * __expf(0.125f * sacc[mi][nf][0]) * iv[mi][0];
                        const float w1 = f1 * __expf(0.125f * sacc[mi][nf][1]) * iv[mi][0];
                        const float w2 = f0 * __expf(0.125f * sacc[mi][nf][2]) * iv[mi][1];
                        const float w3 = f1 * __expf(0.125f * sacc[mi][nf][3]) * iv[mi][1];
                        const int r0 = m0 + wm0 + 16 * mi + g;
                        float* Wp = wts + (long long)z * TT + (long long)r0 * 2048 + n;
                        *(float2*)Wp = make_float2(w0, w1);
                        *(float2*)(Wp + 8LL * 2048) = make_float2(w2, w3);
                        cvt2(w0, w1, wh[mi][2 * j], wl[mi][2 * j]);
                        cvt2(w2, w3, wh[mi][2 * j + 1], wl[mi][2 * j + 1]);
                    }
                }
                const uint32_t vcb = (uint32_t)(wni * 64 + kv * 32) + bColB;
#pragma unroll
                for (int cfp = 0; cfp < 4; ++cfp) {
                    uint32_t vh4[4], vl4[4];
                    ldsm4(vh4, vh + (cfp * 16 + bRow) * 144 + vcb);
                    ldsm4(vl4, vl + (cfp * 16 + bRow) * 144 + vcb);
#pragma unroll
                    for (int mi = 0; mi < 2; ++mi)
#pragma unroll
                        for (int j = 0; j < 2; ++j) {
                            float* o = oacc[mi][2 * cfp + j];
                            mma_bf16(o, wh[mi], vh4 + 2 * j);
                            mma_bf16(o, wh[mi], vl4 + 2 * j);
                            mma_bf16(o, wl[mi], vh4 + 2 * j);
                        }
                }
            }
        }
        __syncthreads();
    }

    if (PASS == 1) {
#pragma unroll
        for (int mi = 0; mi < 2; ++mi)
#pragma unroll
            for (int j = 0; j < 2; ++j) {
                float v = rs[mi][j];
                v += __shfl_xor_sync(0xffffffffu, v, 1);
                v += __shfl_xor_sync(0xffffffffu, v, 2);
                if (t4 == 0) rsc[(wm0 + 16 * mi + g + 8 * j) * 2 + wni] = v;
            }
        __syncthreads();
        if (tid < 128) {
            const float s = rsc[tid * 2] + rsc[tid * 2 + 1];
            invp[z * 2048 + m0 + tid] = (s > 0.f) ? (1.f / s) : 0.f;
        }
    } else {
        float* Osc = (float*)(smraw + 36864);   // overlay on K buffers
        if (wni == 0) {
#pragma unroll
            for (int mi = 0; mi < 2; ++mi)
#pragma unroll
                for (int cf = 0; cf < 8; ++cf) {
                    const int r0 = wm0 + 16 * mi + g, c = 8 * cf + 2 * t4;
                    *(float2*)(Osc + r0 * 66 + c) = make_float2(oacc[mi][cf][0], oacc[mi][cf][1]);
                    *(float2*)(Osc + (r0 + 8) * 66 + c) = make_float2(oacc[mi][cf][2], oacc[mi][cf][3]);
                }
        }
        __syncthreads();
        if (wni == 1) {
#pragma unroll
            for (int mi = 0; mi < 2; ++mi)
#pragma unroll
                for (int cf = 0; cf < 8; ++cf) {
                    const int r0 = wm0 + 16 * mi + g, c = 8 * cf + 2 * t4;
                    float2 p0 = *(float2*)(Osc + r0 * 66 + c);
                    float2 p1 = *(float2*)(Osc + (r0 + 8) * 66 + c);
                    float* o0 = Og + ((long long)(gb * 2048 + m0 + r0)) * 1024 + (z & 15) * 64 + c;
                    float* o1 = Og + ((long long)(gb * 2048 + m0 + r0 + 8)) * 1024 + (z & 15) * 64 + c;
                    *(float2*)o0 = make_float2(p0.x + oacc[mi][cf][0], p0.y + oacc[mi][cf][1]);
                    *(float2*)o1 = make_float2(p1.x + oacc[mi][cf][2], p1.y + oacc[mi][cf][3]);
                }
        }
    }
}

// ---------------------------------------------------------------------------
// bf16x3 warp-MMA GEMM, 512 threads / 16 warps (4m x 4n), warp tile 32x32.
// C(128 x 128 per CTA) = A(M,K) * B(N,K)^T
// EPI 0: plain fp32 store (out-proj).  EPI 1: QKV routing -> bf16 split arrays.
// ---------------------------------------------------------------------------
template <int EPI>
__global__ __launch_bounds__(512, 1) void gemm_mma(
    const float* __restrict__ A, long long lda,
    const float* __restrict__ B0, const float* __restrict__ B1, const float* __restrict__ B2,
    long long ldb,
    float* __restrict__ C, long long ldc, int Kd)
{
    constexpr int SAP = 40;                 // padded stride (bf16), 80 B rows
    constexpr int ASZ = 128 * SAP;
    constexpr int BSZ = 128 * SAP;
    constexpr int STG = 2 * (ASZ + BSZ);

    extern __shared__ unsigned short smem[];
    const uint32_t smB = smem_u32(smem);

    const int tid = threadIdx.x, lane = tid & 31, wid = tid >> 5;
    const int g = lane >> 2, t4 = lane & 3;
    const int wm0 = (wid >> 2) * 32;        // 4 m-warps
    const int wn0 = (wid & 3) * 32;         // 4 n-warps
    const int m0 = blockIdx.y * 128, n0 = blockIdx.x * 128;

    const uint32_t aRow = (uint32_t)(lane & 15);
    const uint32_t aColB = (uint32_t)((lane >> 4) * 16);
    const uint32_t bRow = (uint32_t)(((lane >> 4) & 1) * 8 + (lane & 7));
    const uint32_t bColB = (uint32_t)(((lane >> 3) & 1) * 16);

    const float* Ab = A;
    const float* Bb;
    if (EPI == 1) {
        const int mat = blockIdx.x >> 3;
        const float* Bs = (mat == 0) ? B0 : ((mat == 1) ? B1 : B2);
        Bb = Bs + (long long)((blockIdx.x & 7) * 128) * ldb;
    } else {
        Bb = B0 + (long long)n0 * ldb;
    }

    float acc[2][4][4];
#pragma unroll
    for (int mi = 0; mi < 2; ++mi)
#pragma unroll
        for (int ni = 0; ni < 4; ++ni)
#pragma unroll
            for (int j = 0; j < 4; ++j) acc[mi][ni][j] = 0.f;

    float4 aR[2];
    float4 bR[2];

    auto loadA = [&](int s) {
        const int k0 = s << 5;
#pragma unroll
        for (int i = 0; i < 2; ++i) {
            const int idx = tid + 512 * i, r = idx >> 3, q = idx & 7;
            aR[i] = *(const float4*)(Ab + (long long)(m0 + r) * lda + (k0 + 4 * q));
        }
    };
    auto loadB = [&](int s) {
        const int k0 = s << 5;
#pragma unroll
        for (int i = 0; i < 2; ++i) {
            const int idx = tid + 512 * i, r = idx >> 3, q = idx & 7;
            bR[i] = *(const float4*)(Bb + (long long)r * ldb + (k0 + 4 * q));
        }
    };
    auto stsA = [&](int st) {
        unsigned short* Ah = smem + st * STG;
        unsigned short* Al = Ah + ASZ;
#pragma unroll
        for (int i = 0; i < 2; ++i) {
            const int idx = tid + 512 * i, r = idx >> 3, q = idx & 7;
            uint32_t h01, l01, h23, l23;
            cvt2(aR[i].x, aR[i].y, h01, l01);
            cvt2(aR[i].z, aR[i].w, h23, l23);
            *(uint2*)(Ah + r * SAP + 4 * q) = make_uint2(h01, h23);
            *(uint2*)(Al + r * SAP + 4 * q) = make_uint2(l01, l23);
        }
    };
    auto stsB = [&](int st) {
        unsigned short* Bh = smem + st * STG + 2 * ASZ;
        unsigned short* Bl = Bh + BSZ;
#pragma unroll
        for (int i = 0; i < 2; ++i) {
            const int idx = tid + 512 * i, r = idx >> 3, q = idx & 7;
            uint32_t h01, l01, h23, l23;
            cvt2(bR[i].x, bR[i].y, h01, l01);
            cvt2(bR[i].z, bR[i].w, h23, l23);
            *(uint2*)(Bh + r * SAP + 4 * q) = make_uint2(h01, h23);
            *(uint2*)(Bl + r * SAP + 4 * q) = make_uint2(l01, l23);
        }
    };
    auto compute = [&](int st) {
        const uint32_t AhB = smB + (uint32_t)(st * STG) * 2;
        const uint32_t AlB = AhB + ASZ * 2;
        const uint32_t BhB = AhB + 2 * ASZ * 2;
        const uint32_t BlB = BhB + BSZ * 2;
#pragma unroll
        for (int ks = 0; ks < 2; ++ks) {
            const uint32_t ac = (uint32_t)(ks * 32) + aColB;
            const uint32_t bc = (uint32_t)(ks * 32) + bColB;
            uint32_t ah[2][4], al[2][4];
#pragma unroll
            for (int mi = 0; mi < 2; ++mi) {
                ldsm4(ah[mi], AhB + (wm0 + 16 * mi + aRow) * 80 + ac);
                ldsm4(al[mi], AlB + (wm0 + 16 * mi + aRow) * 80 + ac);
            }
#pragma unroll
            for (int nfp = 0; nfp < 2; ++nfp) {
                uint32_t bh4[4], bl4[4];
                ldsm4(bh4, BhB + (wn0 + nfp * 16 + bRow) * 80 + bc);
                ldsm4(bl4, BlB + (wn0 + nfp * 16 + bRow) * 80 + bc);
#pragma unroll
                for (int mi = 0; mi < 2; ++mi)
#pragma unroll
                    for (int j = 0; j < 2; ++j) {
                        float* o = acc[mi][2 * nfp + j];
                        mma_bf16(o, ah[mi], bh4 + 2 * j);
                        mma_bf16(o, ah[mi], bl4 + 2 * j);
                        mma_bf16(o, al[mi], bh4 + 2 * j);
                    }
            }
        }
    };

    const int nS = Kd >> 5;
    loadA(0); loadB(0);
    stsA(0);  stsB(0);
    __syncthreads();
    for (int s = 0; s < nS; ++s) {
        const int st = s & 1;
        if (s + 1 < nS) { loadA(s + 1); loadB(s + 1); }
        compute(st);
        __syncthreads();
        if (s + 1 < nS) { stsA(st ^ 1); stsB(st ^ 1); __syncthreads(); }
    }

#pragma unroll
    for (int mi = 0; mi < 2; ++mi) {
        const int r0 = wm0 + 16 * mi + g, r1 = r0 + 8;
#pragma unroll
        for (int ni = 0; ni < 4; ++ni) {
            const int c = wn0 + 8 * ni + 2 * t4;
            const float v0 = acc[mi][ni][0], v1 = acc[mi][ni][1];
            const float v2 = acc[mi][ni][2], v3 = acc[mi][ni][3];
            if (EPI == 0) {
                *(float2*)(C + (long long)(m0 + r0) * ldc + n0 + c) = make_float2(v0, v1);
                *(float2*)(C + (long long)(m0 + r1) * ldc + n0 + c) = make_float2(v2, v3);
            } else {
                const int nloc = (blockIdx.x & 7) * 128 + c;
                const int h = nloc >> 6, k = nloc & 63;
                const int mat = blockIdx.x >> 3;
                const int mr0 = m0 + r0, b0 = mr0 >> 11, tt0 = mr0 & 2047;
                const int mr1 = m0 + r1, b1 = mr1 >> 11, tt1 = mr1 & 2047;
                uint32_t h01, l01, h23, l23;
                cvt2(v0, v1, h01, l01);
                cvt2(v2, v3, h23, l23);
                if (mat < 2) {
                    unsigned short* dh = (mat == 0) ? g_Qh : g_Kh;
                    unsigned short* dl = (mat == 0) ? g_Ql : g_Kl;
                    const long long o0 = ((long long)((b0 * 16 + h) * 2048 + tt0)) * 64 + k;
                    const long long o1 = ((long long)((b1 * 16 + h) * 2048 + tt1)) * 64 + k;
                    *(uint32_t*)&dh[o0] = h01; *(uint32_t*)&dl[o0] = l01;
                    *(uint32_t*)&dh[o1] = h23; *(uint32_t*)&dl[o1] = l23;
                } else {
                    const long long c0 = ((long long)((b0 * 16 + h) * 64 + k)) * 2048;
                    const long long c1 = c0 + 2048;
                    g_Vth[c0 + tt0] = (unsigned short)(h01 & 0xFFFF);
                    g_Vth[c1 + tt0] = (unsigned short)(h01 >> 16);
                    g_Vtl[c0 + tt0] = (unsigned short)(l01 & 0xFFFF);
                    g_Vtl[c1 + tt0] = (unsigned short)(l01 >> 16);
                    g_Vth[c0 + tt1] = (unsigned short)(h23 & 0xFFFF);
                    g_Vth[c1 + tt1] = (unsigned short)(h23 >> 16);
                    g_Vtl[c0 + tt1] = (unsigned short)(l23 & 0xFFFF);
                    g_Vtl[c1 + tt1] = (unsigned short)(l23 >> 16);
                }
            }
        }
    }
}

// ---------------------------------------------------------------------------
// kernel_launch: x, mask(int32), W_Q, W_K, W_V, W_O -> d_out = [output | weights]
// ---------------------------------------------------------------------------
extern "C" void kernel_launch(void* const* d_in, const int* in_sizes, int n_in,
                              void* d_out, int out_size)
{
    const float* x    = (const float*)d_in[0];
    const int*   mask = (const int*)d_in[1];
    const float* WQ   = (const float*)d_in[2];
    const float* WK   = (const float*)d_in[3];
    const float* WV   = (const float*)d_in[4];
    const float* WO   = (const float*)d_in[5];

    float* out = (float*)d_out;
    float* wts = out + OUT_ELEMS;

    unsigned short *Qh, *Ql, *Kh, *Kl, *Vth, *Vtl;
    float *Op, *invp;
    cudaGetSymbolAddress((void**)&Qh,  g_Qh);
    cudaGetSymbolAddress((void**)&Ql,  g_Ql);
    cudaGetSymbolAddress((void**)&Kh,  g_Kh);
    cudaGetSymbolAddress((void**)&Kl,  g_Kl);
    cudaGetSymbolAddress((void**)&Vth, g_Vth);
    cudaGetSymbolAddress((void**)&Vtl, g_Vtl);
    cudaGetSymbolAddress((void**)&Op,  g_O);
    cudaGetSymbolAddress((void**)&invp, g_inv);

    const int SMG = 2 * 2 * (128 * 40 + 128 * 40) * 2;   // 81920
    const int SM1 = 38912;
    const int SM2 = 112640;
    cudaFuncSetAttribute(gemm_mma<1>, cudaFuncAttributeMaxDynamicSharedMemorySize, SMG);
    cudaFuncSetAttribute(gemm_mma<0>, cudaFuncAttributeMaxDynamicSharedMemorySize, SMG);
    cudaFuncSetAttribute(attn_kernel<1>, cudaFuncAttributeMaxDynamicSharedMemorySize, SM1);
    cudaFuncSetAttribute(attn_kernel<2>, cudaFuncAttributeMaxDynamicSharedMemorySize, SM2);

    // 1) Fused QKV projection -> bf16 split Q,K and transposed V
    gemm_mma<1><<<dim3(24, 32, 1), 512, SMG>>>(
        x, DMODEL, WQ, WK, WV, DMODEL, nullptr, 0, DMODEL);

    // 2) Pass 1: row sums -> inv (single-term bf16 S, zero TT traffic)
    attn_kernel<1><<<dim3(16, 32), 256, SM1>>>(
        Qh, Ql, Kh, Kl, Vth, Vtl, mask, wts, invp, Op);

    // 3) Pass 2: W written once + O = W*V fused (bf16x3)
    attn_kernel<2><<<dim3(16, 32), 256, SM2>>>(
        Qh, Ql, Kh, Kl, Vth, Vtl, mask, wts, invp, Op);

    // 4) Output projection
    gemm_mma<0><<<dim3(8, 32, 1), 512, SMG>>>(
        Op, DMODEL, WO, nullptr, nullptr, DMODEL, out, DMODEL, DMODEL);
}